// round 11
// baseline (speedup 1.0000x reference)
#include <cuda_runtime.h>
#include <cstdint>
#include <math.h>

#define BB 32
#define NN 512
#define DD 1024
#define MMR (BB*NN)          // 16384

#define BM 128
#define BN 128
#define BK 32
#define NSTAGE 3
#define STG_BYTES 32768      // A 16KB + B 16KB per stage
#define KITERS (DD/BK)       // 32

__device__ float g_yacc[MMR];
__device__ float g_qacc[MMR];
__device__ float g_Wt[DD*DD];  // [n][k]: rows 0-511 = W1^T, 512-1023 = Wc1^T (tf32-RN, bias-compensated)

// ---------------- helpers ----------------
__device__ __forceinline__ uint32_t smem_u32(const void* p) {
    uint32_t a;
    asm("{ .reg .u64 t; cvta.to.shared.u64 t, %1; cvt.u32.u64 %0, t; }" : "=r"(a) : "l"(p));
    return a;
}
__device__ __forceinline__ void cp16(uint32_t dst, const void* src) {
    asm volatile("cp.async.cg.shared.global [%0], [%1], 16;" :: "r"(dst), "l"(src));
}
#define CPCOMMIT() asm volatile("cp.async.commit_group;")
#define CPWAIT2()  asm volatile("cp.async.wait_group 2;")
#define CPWAIT1()  asm volatile("cp.async.wait_group 1;")
#define CPWAIT0()  asm volatile("cp.async.wait_group 0;")

#define MBAR_INIT(mb, c) asm volatile("mbarrier.init.shared.b64 [%0], %1;" :: "r"(mb), "r"((uint32_t)(c)) : "memory")
#define MBAR_ARRIVE(mb)  asm volatile("mbarrier.arrive.shared.b64 _, [%0];" :: "r"(mb) : "memory")
#define MBAR_WAIT(mb, par) do {                                                      \
    uint32_t _m = (mb), _p = (par), _d;                                              \
    asm volatile("{\n\t.reg .pred p;\n\t"                                            \
        "mbarrier.try_wait.parity.acquire.cta.shared::cta.b64 p, [%1], %2;\n\t"      \
        "selp.b32 %0, 1, 0, p;\n\t}" : "=r"(_d) : "r"(_m), "r"(_p) : "memory");      \
    if (!_d) { asm volatile("{\n\t.reg .pred P1;\n\tWL_%=:\n\t"                      \
        "mbarrier.try_wait.parity.acquire.cta.shared::cta.b64 P1, [%0], %1, 0x989680;\n\t" \
        "@P1 bra.uni WD_%=;\n\tbra.uni WL_%=;\n\tWD_%=:\n\t}" :: "r"(_m), "r"(_p) : "memory"); } \
} while (0)

#define LDSM4(r, addr) \
    asm volatile("ldmatrix.sync.aligned.m8n8.x4.shared.b16 {%0,%1,%2,%3}, [%4];" \
        : "=r"((r)[0]), "=r"((r)[1]), "=r"((r)[2]), "=r"((r)[3]) : "r"(addr))

#define MMA_TF32(c, a, b0, b1) \
    asm volatile("mma.sync.aligned.m16n8k8.row.col.f32.tf32.tf32.f32 " \
        "{%0,%1,%2,%3}, {%4,%5,%6,%7}, {%8,%9}, {%0,%1,%2,%3};" \
        : "+f"((c)[0]), "+f"((c)[1]), "+f"((c)[2]), "+f"((c)[3]) \
        : "r"((a)[0]), "r"((a)[1]), "r"((a)[2]), "r"((a)[3]), "r"(b0), "r"(b1))

__device__ __forceinline__ float rna_tf32(float v) {
    uint32_t u; asm("cvt.rna.tf32.f32 %0, %1;" : "=r"(u) : "f"(v));
    return __uint_as_float(u);
}

// MUFU-free shifted softplus: max(x,0) + ln(1+e^-|x|) - ln2
__device__ __forceinline__ float sspf(float x) {
    float ax = fabsf(x);
    float u  = fmaxf(ax * -1.4426950408889634f, -30.0f);
    float fl = floorf(u);
    float z  = (u - fl) * 0.6931471805599453f;
    float p  = 1.9841270e-4f;
    p = fmaf(p, z, 1.3888889e-3f);
    p = fmaf(p, z, 8.3333333e-3f);
    p = fmaf(p, z, 4.1666667e-2f);
    p = fmaf(p, z, 1.6666667e-1f);
    p = fmaf(p, z, 0.5f);
    p = fmaf(p, z, 1.0f);
    p = fmaf(p, z, 1.0f);
    float t = __int_as_float(((int)fl + 127) << 23) * p;
    float den = 2.0f + t;
    float r = __int_as_float(0x7EF311C4u - __float_as_uint(den));
    r = r * fmaf(-den, r, 2.0f);
    r = r * fmaf(-den, r, 2.0f);
    float w  = t * r;
    float w2 = w * w;
    float q  = 0.22222222f;
    q = fmaf(q, w2, 0.28571429f);
    q = fmaf(q, w2, 0.4f);
    q = fmaf(q, w2, 0.66666667f);
    q = fmaf(q, w2, 2.0f);
    return fmaxf(x, 0.0f) + w * q - 0.6931471805599453f;
}

// ---------------- prep: weight transpose (tf32-RN + bias comp), float4 stores, + zero accumulators ----------------
__global__ void wtrans_kernel(const float* __restrict__ W1, const float* __restrict__ Wc1,
                              float* __restrict__ out) {
    __shared__ float t[32][33];
    const int tx = threadIdx.x, ty = threadIdx.y;
    const int n0 = blockIdx.x * 32, k0 = blockIdx.y * 32;
    const int n = n0 + tx;
    const float* Wsrc = (n < 512) ? (W1 + n) : (Wc1 + (n - 512));
    #pragma unroll
    for (int i = 0; i < 4; i++) {
        int k = k0 + ty * 4 + i;
        // A is fed raw f32 -> HW truncation to tf32 shrinks |a| by E[eps]~0.72*2^-11.
        // Pre-scale W to cancel the bias in expectation.
        t[ty * 4 + i][tx] = rna_tf32(Wsrc[k * 512] * 1.000352f);
    }
    __syncthreads();
    {
        float4 v = make_float4(t[ty * 4 + 0][tx], t[ty * 4 + 1][tx],
                               t[ty * 4 + 2][tx], t[ty * 4 + 3][tx]);
        *(float4*)&g_Wt[(size_t)(n0 + tx) * DD + k0 + ty * 4] = v;
    }
    int gi = (blockIdx.y * 32 + blockIdx.x) * 256 + ty * 32 + tx;
    if (gi < MMR) { g_yacc[gi] = 0.0f; g_qacc[gi] = 0.0f; }
    if (gi < BB) out[gi] = 0.0f;
}

// ---------------- tf32 mma.sync GEMM + fused ssp epilogue, mbarrier-pipelined (no per-iter syncthreads) ----------------
// CTA: 128x128 tile, BK=32, 8 warps (2 M x 4 N), warp tile 64x32 via m16n8k8.
// 3-stage cp.async ring; per-stage full/empty mbarriers (256 arrivals each) replace the CTA rally.
extern __shared__ char dynsm[];
__global__ __launch_bounds__(256, 2)
void mlp_mma(const float* __restrict__ rep,
             const float* __restrict__ b1,  const float* __restrict__ W2,
             const float* __restrict__ bc1, const float* __restrict__ Wc2)
{
    const int tid  = threadIdx.x;
    const int wid  = tid >> 5, lane = tid & 31;
    const int mw   = wid >> 2, nw = wid & 3;
    const int m0   = blockIdx.x * BM;
    const int n0   = blockIdx.y * BN;

    const uint32_t sb = smem_u32(dynsm);
    float* biasS  = (float*)(dynsm + NSTAGE * STG_BYTES);
    float* w2S    = biasS + BN;
    float* rowsum = w2S + BN;
    const uint32_t barBase = sb + NSTAGE * STG_BYTES + (2 * BN + BM) * 4;
    #define FULLB(s) (barBase + (s) * 16)
    #define EMPTYB(s) (barBase + (s) * 16 + 8)

    if (tid == 0) {
        #pragma unroll
        for (int s = 0; s < NSTAGE; s++) { MBAR_INIT(FULLB(s), 256); MBAR_INIT(EMPTYB(s), 256); }
    }
    if (tid < BN) {
        const float* bsrc = (n0 >= 512) ? bc1 : b1;
        const float* wsrc = (n0 >= 512) ? Wc2 : W2;
        int ch = (n0 & 511) + tid;
        biasS[tid]  = bsrc[ch];
        w2S[tid]    = wsrc[ch];
        rowsum[tid] = 0.0f;
    }

    // cp.async assignments: 4 A chunks + 4 B chunks of 16B per thread
    uint32_t dstOff[4];
    const float* srcA[4];
    const float* srcB[4];
    #pragma unroll
    for (int l = 0; l < 4; l++) {
        int idx = tid + l * 256;          // 0..1023
        int row = idx >> 3, kc = idx & 7;
        dstOff[l] = row * 128 + ((kc ^ (row & 7)) << 4);
        srcA[l] = rep  + (size_t)(m0 + row) * DD + kc * 4;
        srcB[l] = g_Wt + (size_t)(n0 + row) * DD + kc * 4;
    }

    // ldmatrix per-lane base addresses (swizzled, 128B rows)
    const int g  = lane >> 3, li = lane & 7;
    const int rowA = mw * 64 + (g & 1) * 8 + li;
    const uint32_t addrA0 = rowA * 128 + ((((g >> 1) ^ rowA) & 7) << 4);
    const int rowB = nw * 32 + (g >> 1) * 8 + li;
    const uint32_t addrB0 = rowB * 128 + ((((g & 1) ^ rowB) & 7) << 4);

    float c[4][4][4];
    #pragma unroll
    for (int i = 0; i < 4; i++)
        #pragma unroll
        for (int j = 0; j < 4; j++)
            #pragma unroll
            for (int e = 0; e < 4; e++) c[i][j][e] = 0.0f;

    __syncthreads();   // mbarrier init + biasS/rowsum visible

    // prologue: fill stages 0,1 (no empty-wait needed for the first pass of each slot)
    #pragma unroll
    for (int s = 0; s < 2; s++) {
        uint32_t a = sb + s * STG_BYTES, b = a + 16384;
        #pragma unroll
        for (int l = 0; l < 4; l++) {
            cp16(a + dstOff[l], srcA[l] + s * BK);
            cp16(b + dstOff[l], srcB[l] + s * BK);
        }
        CPCOMMIT();
    }

    int fullPh[NSTAGE]  = {0, 0, 0};
    int emptyPh[NSTAGE] = {0, 0, 0};

    for (int it = 0; it < KITERS; it++) {
        const int s = it % NSTAGE;
        // produce stage it+2 into slot (it+2)%3
        if (it + 2 < KITERS) {
            const int s2 = (it + 2) % NSTAGE;
            if (it + 2 >= NSTAGE) {            // slot reuse: wait until fill#k-1 consumed
                MBAR_WAIT(EMPTYB(s2), emptyPh[s2]); emptyPh[s2] ^= 1;
            }
            uint32_t a = sb + s2 * STG_BYTES, b = a + 16384;
            #pragma unroll
            for (int l = 0; l < 4; l++) {
                cp16(a + dstOff[l], srcA[l] + (it + 2) * BK);
                cp16(b + dstOff[l], srcB[l] + (it + 2) * BK);
            }
            CPCOMMIT();
        }
        // my stage-it copies complete?
        if (it + 2 < KITERS)       CPWAIT2();
        else if (it + 1 < KITERS)  CPWAIT1();
        else                       CPWAIT0();
        MBAR_ARRIVE(FULLB(s));                       // release my stage-it data
        MBAR_WAIT(FULLB(s), fullPh[s]); fullPh[s] ^= 1;   // acquire all 256

        const uint32_t sA = sb + s * STG_BYTES;
        const uint32_t sB = sA + 16384;
        #pragma unroll
        for (int h = 0; h < 4; h++) {
            const uint32_t kx = h << 5;
            uint32_t a[4][4], b[2][4];
            #pragma unroll
            for (int mt = 0; mt < 4; mt++)
                LDSM4(a[mt], sA + ((addrA0 + mt * 2048) ^ kx));
            #pragma unroll
            for (int p = 0; p < 2; p++)
                LDSM4(b[p], sB + ((addrB0 + p * 2048) ^ kx));
            #pragma unroll
            for (int mt = 0; mt < 4; mt++) {
                #pragma unroll
                for (int nt = 0; nt < 4; nt++)
                    MMA_TF32(c[mt][nt], a[mt], b[nt >> 1][(nt & 1) * 2],
                             b[nt >> 1][(nt & 1) * 2 + 1]);
            }
        }
        MBAR_ARRIVE(EMPTYB(s));                      // free slot for stage it+3
    }

    // epilogue: z+bias -> ssp -> *w2 -> per-row reduce
    float bcol[8], wcol[8];
    #pragma unroll
    for (int nt = 0; nt < 4; nt++)
        #pragma unroll
        for (int e = 0; e < 2; e++) {
            int col = nw * 32 + nt * 8 + 2 * (lane & 3) + e;
            bcol[nt * 2 + e] = biasS[col];
            wcol[nt * 2 + e] = w2S[col];
        }

    float prow[8];
    #pragma unroll
    for (int i = 0; i < 8; i++) prow[i] = 0.0f;
    #pragma unroll
    for (int mt = 0; mt < 4; mt++)
        #pragma unroll
        for (int nt = 0; nt < 4; nt++)
            #pragma unroll
            for (int e = 0; e < 4; e++) {
                float z = c[mt][nt][e] + bcol[nt * 2 + (e & 1)];
                prow[mt * 2 + (e >> 1)] += sspf(z) * wcol[nt * 2 + (e & 1)];
            }
    #pragma unroll
    for (int i = 0; i < 8; i++) {
        prow[i] += __shfl_xor_sync(0xFFFFFFFF, prow[i], 1);
        prow[i] += __shfl_xor_sync(0xFFFFFFFF, prow[i], 2);
    }
    if ((lane & 3) == 0) {
        #pragma unroll
        for (int mt = 0; mt < 4; mt++)
            #pragma unroll
            for (int hh = 0; hh < 2; hh++) {
                int rl = mw * 64 + mt * 16 + hh * 8 + (lane >> 2);
                atomicAdd(&rowsum[rl], prow[mt * 2 + hh]);
            }
    }
    __syncthreads();
    if (tid < BM) {
        float* dst = (n0 >= 512) ? g_qacc : g_yacc;
        atomicAdd(&dst[m0 + tid], rowsum[tid]);
    }
}

// ---------------- coulomb + pool (MUFU-free, float4 layout, 512 blocks) ----------------
#define CHUNK 32
__global__ __launch_bounds__(256)
void coulomb_kernel(const float* __restrict__ R, const float* __restrict__ mask,
                    const float* __restrict__ b2p, const float* __restrict__ bc2p,
                    float* __restrict__ out)
{
    const int b = blockIdx.x / (NN / CHUNK);
    const int chunk = blockIdx.x % (NN / CHUNK);
    const int tid = threadIdx.x;
    __shared__ float4 pt[NN];
    __shared__ float red[8];
    const float b2v = b2p[0], bc2v = bc2p[0];

    for (int n = tid; n < NN; n += 256) {
        float mk = mask[b * NN + n];
        float q  = (g_qacc[b * NN + n] + bc2v) * mk;
        const float* r = &R[(b * NN + n) * 3];
        pt[n] = make_float4(r[0], r[1], r[2], q);
    }
    __syncthreads();

    float acc = 0.0f;
    const int i0 = chunk * CHUNK;
    #pragma unroll 1
    for (int i = i0; i < i0 + CHUNK; i += 2) {
        const float4 p0 = pt[i];
        const float4 p1 = pt[i + 1];
        #pragma unroll 2
        for (int j = tid; j < NN; j += 256) {
            float4 pj = pt[j];
            {
                float dx = p0.x - pj.x, dy = p0.y - pj.y, dz = p0.z - pj.z;
                float d2 = fmaf(dx, dx, fmaf(dy, dy, dz * dz));
                float r = __int_as_float(0x7EF311C4u - __float_as_uint(d2));
                r = r * fmaf(-d2, r, 2.0f);
                r = r * fmaf(-d2, r, 2.0f);
                float hr = __int_as_float(0x5F3759DFu - (__float_as_uint(d2) >> 1));
                hr = hr * fmaf(-0.5f * d2 * hr, hr, 1.5f);
                float u = 1e-5f * hr;
                float inv2 = r * fmaf(u, fmaf(3.0f, u, -2.0f), 1.0f);
                float tt = p0.w * pj.w * inv2;
                acc += (j == i) ? 0.0f : tt;
            }
            {
                float dx = p1.x - pj.x, dy = p1.y - pj.y, dz = p1.z - pj.z;
                float d2 = fmaf(dx, dx, fmaf(dy, dy, dz * dz));
                float r = __int_as_float(0x7EF311C4u - __float_as_uint(d2));
                r = r * fmaf(-d2, r, 2.0f);
                r = r * fmaf(-d2, r, 2.0f);
                float hr = __int_as_float(0x5F3759DFu - (__float_as_uint(d2) >> 1));
                hr = hr * fmaf(-0.5f * d2 * hr, hr, 1.5f);
                float u = 1e-5f * hr;
                float inv2 = r * fmaf(u, fmaf(3.0f, u, -2.0f), 1.0f);
                float tt = p1.w * pj.w * inv2;
                acc += (j == i + 1) ? 0.0f : tt;
            }
        }
    }
    for (int i = i0 + tid; i < i0 + CHUNK; i += 256)
        acc += (g_yacc[b * NN + i] + b2v) * mask[b * NN + i];

    #pragma unroll
    for (int off = 16; off > 0; off >>= 1) acc += __shfl_down_sync(0xFFFFFFFF, acc, off);
    if ((tid & 31) == 0) red[tid >> 5] = acc;
    __syncthreads();
    if (tid < 8) {
        float v = red[tid];
        #pragma unroll
        for (int off = 4; off > 0; off >>= 1) v += __shfl_down_sync(0xFF, v, off);
        if (tid == 0) atomicAdd(&out[b], v);
    }
}

// ---------------- host ----------------
extern "C" void kernel_launch(void* const* d_in, const int* in_sizes, int n_in,
                              void* d_out, int out_size) {
    const float* rep  = (const float*)d_in[0];
    const float* R    = (const float*)d_in[1];
    const float* mask = (const float*)d_in[2];
    const float* W1   = (const float*)d_in[3];
    const float* b1   = (const float*)d_in[4];
    const float* W2   = (const float*)d_in[5];
    const float* b2   = (const float*)d_in[6];
    const float* Wc1  = (const float*)d_in[7];
    const float* bc1  = (const float*)d_in[8];
    const float* Wc2  = (const float*)d_in[9];
    const float* bc2  = (const float*)d_in[10];
    float* out = (float*)d_out;

    const int DYN = NSTAGE * STG_BYTES + (BN * 2 + BM) * 4 + 64;   // +mbarriers
    cudaFuncSetAttribute(mlp_mma, cudaFuncAttributeMaxDynamicSharedMemorySize, DYN);

    wtrans_kernel<<<dim3(32, 32), dim3(32, 8)>>>(W1, Wc1, out);
    mlp_mma<<<dim3(MMR / BM, DD / BN), 256, DYN>>>(rep, b1, W2, bc1, Wc2);
    coulomb_kernel<<<BB * (NN / CHUNK), 256>>>(R, mask, b2, bc2, out);
}

// round 12
// speedup vs baseline: 1.0149x; 1.0149x over previous
#include <cuda_runtime.h>
#include <cstdint>
#include <math.h>

#define BB 32
#define NN 512
#define DD 1024
#define MMR (BB*NN)          // 16384

#define BM 128
#define BN 128
#define BK 32
#define NSTAGE 3
#define STG_BYTES 32768      // A 16KB + B 16KB per stage
#define KITERS (DD/BK)       // 32

__device__ float g_yacc[MMR];
__device__ float g_qacc[MMR];
__device__ float g_Wt[DD*DD];  // [n][k]: rows 0-511 = W1^T, 512-1023 = Wc1^T (tf32-RN, bias-compensated)

// ---------------- helpers ----------------
__device__ __forceinline__ uint32_t smem_u32(const void* p) {
    uint32_t a;
    asm("{ .reg .u64 t; cvta.to.shared.u64 t, %1; cvt.u32.u64 %0, t; }" : "=r"(a) : "l"(p));
    return a;
}
__device__ __forceinline__ void cp16(uint32_t dst, const void* src) {
    asm volatile("cp.async.cg.shared.global [%0], [%1], 16;" :: "r"(dst), "l"(src));
}
#define CPCOMMIT() asm volatile("cp.async.commit_group;")
#define CPWAIT1()  asm volatile("cp.async.wait_group 1;")

#define LDSM4(r, addr) \
    asm volatile("ldmatrix.sync.aligned.m8n8.x4.shared.b16 {%0,%1,%2,%3}, [%4];" \
        : "=r"((r)[0]), "=r"((r)[1]), "=r"((r)[2]), "=r"((r)[3]) : "r"(addr))

#define MMA_TF32(c, a, b0, b1) \
    asm volatile("mma.sync.aligned.m16n8k8.row.col.f32.tf32.tf32.f32 " \
        "{%0,%1,%2,%3}, {%4,%5,%6,%7}, {%8,%9}, {%0,%1,%2,%3};" \
        : "+f"((c)[0]), "+f"((c)[1]), "+f"((c)[2]), "+f"((c)[3]) \
        : "r"((a)[0]), "r"((a)[1]), "r"((a)[2]), "r"((a)[3]), "r"(b0), "r"(b1))

__device__ __forceinline__ float rna_tf32(float v) {
    uint32_t u; asm("cvt.rna.tf32.f32 %0, %1;" : "=r"(u) : "f"(v));
    return __uint_as_float(u);
}

// MUFU-free shifted softplus: max(x,0) + ln(1+e^-|x|) - ln2
__device__ __forceinline__ float sspf(float x) {
    float ax = fabsf(x);
    float u  = fmaxf(ax * -1.4426950408889634f, -30.0f);
    float fl = floorf(u);
    float z  = (u - fl) * 0.6931471805599453f;
    float p  = 1.9841270e-4f;
    p = fmaf(p, z, 1.3888889e-3f);
    p = fmaf(p, z, 8.3333333e-3f);
    p = fmaf(p, z, 4.1666667e-2f);
    p = fmaf(p, z, 1.6666667e-1f);
    p = fmaf(p, z, 0.5f);
    p = fmaf(p, z, 1.0f);
    p = fmaf(p, z, 1.0f);
    float t = __int_as_float(((int)fl + 127) << 23) * p;
    float den = 2.0f + t;
    float r = __int_as_float(0x7EF311C4u - __float_as_uint(den));
    r = r * fmaf(-den, r, 2.0f);
    r = r * fmaf(-den, r, 2.0f);
    float w  = t * r;
    float w2 = w * w;
    float q  = 0.22222222f;
    q = fmaf(q, w2, 0.28571429f);
    q = fmaf(q, w2, 0.4f);
    q = fmaf(q, w2, 0.66666667f);
    q = fmaf(q, w2, 2.0f);
    return fmaxf(x, 0.0f) + w * q - 0.6931471805599453f;
}

// ---------------- prep: weight transpose (tf32-RN + bias comp), float4 stores, + zero accumulators ----------------
__global__ void wtrans_kernel(const float* __restrict__ W1, const float* __restrict__ Wc1,
                              float* __restrict__ out) {
    __shared__ float t[32][33];
    const int tx = threadIdx.x, ty = threadIdx.y;
    const int n0 = blockIdx.x * 32, k0 = blockIdx.y * 32;
    const int n = n0 + tx;
    const float* Wsrc = (n < 512) ? (W1 + n) : (Wc1 + (n - 512));
    #pragma unroll
    for (int i = 0; i < 4; i++) {
        int k = k0 + ty * 4 + i;
        // A is fed raw f32 -> HW truncation to tf32 shrinks |a| by E[eps]~0.72*2^-11.
        // Pre-scale W to cancel the bias in expectation.
        t[ty * 4 + i][tx] = rna_tf32(Wsrc[k * 512] * 1.000352f);
    }
    __syncthreads();
    {
        float4 v = make_float4(t[ty * 4 + 0][tx], t[ty * 4 + 1][tx],
                               t[ty * 4 + 2][tx], t[ty * 4 + 3][tx]);
        *(float4*)&g_Wt[(size_t)(n0 + tx) * DD + k0 + ty * 4] = v;
    }
    int gi = (blockIdx.y * 32 + blockIdx.x) * 256 + ty * 32 + tx;
    if (gi < MMR) { g_yacc[gi] = 0.0f; g_qacc[gi] = 0.0f; }
    if (gi < BB) out[gi] = 0.0f;
}

// ---------------- tf32 mma.sync GEMM + fused ssp epilogue (R10 mainloop + warp-rotated h order) ----------------
// CTA: 128x128 tile, BK=32, 8 warps (2 M x 4 N), warp tile 64x32 via m16n8k8.
// SMEM rows 128B (8 x 16B chunks), swizzle: chunk ^= (row & 7).
extern __shared__ char dynsm[];
__global__ __launch_bounds__(256, 2)
void mlp_mma(const float* __restrict__ rep,
             const float* __restrict__ b1,  const float* __restrict__ W2,
             const float* __restrict__ bc1, const float* __restrict__ Wc2)
{
    const int tid  = threadIdx.x;
    const int wid  = tid >> 5, lane = tid & 31;
    const int mw   = wid >> 2, nw = wid & 3;
    const int m0   = blockIdx.x * BM;
    const int n0   = blockIdx.y * BN;
    const int hrot = wid & 3;            // per-warp k8-group rotation

    const uint32_t sb = smem_u32(dynsm);
    float* biasS  = (float*)(dynsm + NSTAGE * STG_BYTES);
    float* w2S    = biasS + BN;
    float* rowsum = w2S + BN;

    if (tid < BN) {
        const float* bsrc = (n0 >= 512) ? bc1 : b1;
        const float* wsrc = (n0 >= 512) ? Wc2 : W2;
        int ch = (n0 & 511) + tid;
        biasS[tid]  = bsrc[ch];
        w2S[tid]    = wsrc[ch];
        rowsum[tid] = 0.0f;
    }

    // cp.async assignments: 4 A chunks + 4 B chunks of 16B per thread
    uint32_t dstOff[4];
    const float* srcA[4];
    const float* srcB[4];
    #pragma unroll
    for (int l = 0; l < 4; l++) {
        int idx = tid + l * 256;          // 0..1023
        int row = idx >> 3, kc = idx & 7;
        dstOff[l] = row * 128 + ((kc ^ (row & 7)) << 4);
        srcA[l] = rep  + (size_t)(m0 + row) * DD + kc * 4;
        srcB[l] = g_Wt + (size_t)(n0 + row) * DD + kc * 4;
    }

    // ldmatrix per-lane base addresses (swizzled, 128B rows)
    const int g  = lane >> 3, li = lane & 7;
    const int rowA = mw * 64 + (g & 1) * 8 + li;
    const int cgA  = g >> 1;
    const uint32_t addrA0 = rowA * 128 + (((cgA ^ rowA) & 7) << 4);
    const int rowB = nw * 32 + (g >> 1) * 8 + li;
    const int cgB  = g & 1;
    const uint32_t addrB0 = rowB * 128 + (((cgB ^ rowB) & 7) << 4);

    float c[4][4][4];
    #pragma unroll
    for (int i = 0; i < 4; i++)
        #pragma unroll
        for (int j = 0; j < 4; j++)
            #pragma unroll
            for (int e = 0; e < 4; e++) c[i][j][e] = 0.0f;

    // prologue: 2 stages in flight
    #pragma unroll
    for (int s = 0; s < 2; s++) {
        uint32_t a = sb + s * STG_BYTES, b = a + 16384;
        #pragma unroll
        for (int l = 0; l < 4; l++) {
            cp16(a + dstOff[l], srcA[l] + s * BK);
            cp16(b + dstOff[l], srcB[l] + s * BK);
        }
        CPCOMMIT();
    }

    for (int it = 0; it < KITERS; it++) {
        CPWAIT1();
        __syncthreads();
        const uint32_t sA = sb + (it % 3) * STG_BYTES;
        const uint32_t sB = sA + 16384;
        const bool more = (it + 2 < KITERS);
        const uint32_t na = sb + ((it + 2) % 3) * STG_BYTES;
        const uint32_t nb = na + 16384;

        #pragma unroll
        for (int hh = 0; hh < 4; hh++) {     // warp w starts at group (w&3): flattens post-barrier LDSM burst
            const int h = (hh + hrot) & 3;
            const uint32_t kx = h << 5;
            uint32_t a[4][4], b[2][4];
            #pragma unroll
            for (int mt = 0; mt < 4; mt++)
                LDSM4(a[mt], sA + ((addrA0 + mt * 2048) ^ kx));
            #pragma unroll
            for (int p = 0; p < 2; p++)
                LDSM4(b[p], sB + ((addrB0 + p * 2048) ^ kx));
            #pragma unroll
            for (int mt = 0; mt < 4; mt++) {
                #pragma unroll
                for (int nt = 0; nt < 4; nt++)
                    MMA_TF32(c[mt][nt], a[mt], b[nt >> 1][(nt & 1) * 2],
                             b[nt >> 1][(nt & 1) * 2 + 1]);
            }
            // interleave next-stage loads between h-groups (off the barrier critical path)
            if (hh == 0 && more) {
                #pragma unroll
                for (int l = 0; l < 4; l++) cp16(na + dstOff[l], srcA[l] + (it + 2) * BK);
            }
            if (hh == 1) {
                if (more) {
                    #pragma unroll
                    for (int l = 0; l < 4; l++) cp16(nb + dstOff[l], srcB[l] + (it + 2) * BK);
                }
                CPCOMMIT();
            }
        }
    }
    __syncthreads();

    // epilogue: z+bias -> ssp -> *w2 -> per-row reduce
    float bcol[8], wcol[8];
    #pragma unroll
    for (int nt = 0; nt < 4; nt++)
        #pragma unroll
        for (int e = 0; e < 2; e++) {
            int col = nw * 32 + nt * 8 + 2 * (lane & 3) + e;
            bcol[nt * 2 + e] = biasS[col];
            wcol[nt * 2 + e] = w2S[col];
        }

    float prow[8];
    #pragma unroll
    for (int i = 0; i < 8; i++) prow[i] = 0.0f;
    #pragma unroll
    for (int mt = 0; mt < 4; mt++)
        #pragma unroll
        for (int nt = 0; nt < 4; nt++)
            #pragma unroll
            for (int e = 0; e < 4; e++) {
                float z = c[mt][nt][e] + bcol[nt * 2 + (e & 1)];
                prow[mt * 2 + (e >> 1)] += sspf(z) * wcol[nt * 2 + (e & 1)];
            }
    #pragma unroll
    for (int i = 0; i < 8; i++) {
        prow[i] += __shfl_xor_sync(0xFFFFFFFF, prow[i], 1);
        prow[i] += __shfl_xor_sync(0xFFFFFFFF, prow[i], 2);
    }
    if ((lane & 3) == 0) {
        #pragma unroll
        for (int mt = 0; mt < 4; mt++)
            #pragma unroll
            for (int hh = 0; hh < 2; hh++) {
                int rl = mw * 64 + mt * 16 + hh * 8 + (lane >> 2);
                atomicAdd(&rowsum[rl], prow[mt * 2 + hh]);
            }
    }
    __syncthreads();
    if (tid < BM) {
        float* dst = (n0 >= 512) ? g_qacc : g_yacc;
        atomicAdd(&dst[m0 + tid], rowsum[tid]);
    }
}

// ---------------- coulomb + pool (MUFU-free, float4 layout, 512 blocks) ----------------
#define CHUNK 32
__global__ __launch_bounds__(256)
void coulomb_kernel(const float* __restrict__ R, const float* __restrict__ mask,
                    const float* __restrict__ b2p, const float* __restrict__ bc2p,
                    float* __restrict__ out)
{
    const int b = blockIdx.x / (NN / CHUNK);
    const int chunk = blockIdx.x % (NN / CHUNK);
    const int tid = threadIdx.x;
    __shared__ float4 pt[NN];
    __shared__ float red[8];
    const float b2v = b2p[0], bc2v = bc2p[0];

    for (int n = tid; n < NN; n += 256) {
        float mk = mask[b * NN + n];
        float q  = (g_qacc[b * NN + n] + bc2v) * mk;
        const float* r = &R[(b * NN + n) * 3];
        pt[n] = make_float4(r[0], r[1], r[2], q);
    }
    __syncthreads();

    float acc = 0.0f;
    const int i0 = chunk * CHUNK;
    #pragma unroll 1
    for (int i = i0; i < i0 + CHUNK; i += 2) {
        const float4 p0 = pt[i];
        const float4 p1 = pt[i + 1];
        #pragma unroll 2
        for (int j = tid; j < NN; j += 256) {
            float4 pj = pt[j];
            {
                float dx = p0.x - pj.x, dy = p0.y - pj.y, dz = p0.z - pj.z;
                float d2 = fmaf(dx, dx, fmaf(dy, dy, dz * dz));
                float r = __int_as_float(0x7EF311C4u - __float_as_uint(d2));
                r = r * fmaf(-d2, r, 2.0f);
                r = r * fmaf(-d2, r, 2.0f);
                float hr = __int_as_float(0x5F3759DFu - (__float_as_uint(d2) >> 1));
                hr = hr * fmaf(-0.5f * d2 * hr, hr, 1.5f);
                float u = 1e-5f * hr;
                float inv2 = r * fmaf(u, fmaf(3.0f, u, -2.0f), 1.0f);
                float tt = p0.w * pj.w * inv2;
                acc += (j == i) ? 0.0f : tt;
            }
            {
                float dx = p1.x - pj.x, dy = p1.y - pj.y, dz = p1.z - pj.z;
                float d2 = fmaf(dx, dx, fmaf(dy, dy, dz * dz));
                float r = __int_as_float(0x7EF311C4u - __float_as_uint(d2));
                r = r * fmaf(-d2, r, 2.0f);
                r = r * fmaf(-d2, r, 2.0f);
                float hr = __int_as_float(0x5F3759DFu - (__float_as_uint(d2) >> 1));
                hr = hr * fmaf(-0.5f * d2 * hr, hr, 1.5f);
                float u = 1e-5f * hr;
                float inv2 = r * fmaf(u, fmaf(3.0f, u, -2.0f), 1.0f);
                float tt = p1.w * pj.w * inv2;
                acc += (j == i + 1) ? 0.0f : tt;
            }
        }
    }
    for (int i = i0 + tid; i < i0 + CHUNK; i += 256)
        acc += (g_yacc[b * NN + i] + b2v) * mask[b * NN + i];

    #pragma unroll
    for (int off = 16; off > 0; off >>= 1) acc += __shfl_down_sync(0xFFFFFFFF, acc, off);
    if ((tid & 31) == 0) red[tid >> 5] = acc;
    __syncthreads();
    if (tid < 8) {
        float v = red[tid];
        #pragma unroll
        for (int off = 4; off > 0; off >>= 1) v += __shfl_down_sync(0xFF, v, off);
        if (tid == 0) atomicAdd(&out[b], v);
    }
}

// ---------------- host ----------------
extern "C" void kernel_launch(void* const* d_in, const int* in_sizes, int n_in,
                              void* d_out, int out_size) {
    const float* rep  = (const float*)d_in[0];
    const float* R    = (const float*)d_in[1];
    const float* mask = (const float*)d_in[2];
    const float* W1   = (const float*)d_in[3];
    const float* b1   = (const float*)d_in[4];
    const float* W2   = (const float*)d_in[5];
    const float* b2   = (const float*)d_in[6];
    const float* Wc1  = (const float*)d_in[7];
    const float* bc1  = (const float*)d_in[8];
    const float* Wc2  = (const float*)d_in[9];
    const float* bc2  = (const float*)d_in[10];
    float* out = (float*)d_out;

    const int DYN = NSTAGE * STG_BYTES + (BN * 2 + BM) * 4;   // 97.5KB
    cudaFuncSetAttribute(mlp_mma, cudaFuncAttributeMaxDynamicSharedMemorySize, DYN);

    wtrans_kernel<<<dim3(32, 32), dim3(32, 8)>>>(W1, Wc1, out);
    mlp_mma<<<dim3(MMR / BM, DD / BN), 256, DYN>>>(rep, b1, W2, bc1, Wc2);
    coulomb_kernel<<<BB * (NN / CHUNK), 256>>>(R, mask, b2, bc2, out);
}

// round 13
// speedup vs baseline: 1.0191x; 1.0041x over previous
#include <cuda_runtime.h>
#include <cstdint>
#include <math.h>

#define BB 32
#define NN 512
#define DD 1024
#define MMR (BB*NN)          // 16384

#define BM 128
#define BN 128
#define BK 32
#define NSTAGE 3
#define STG_BYTES 32768      // A 16KB + B 16KB per stage
#define KITERS (DD/BK)       // 32

__device__ float g_yacc[MMR];
__device__ float g_qacc[MMR];
__device__ float g_Wt[DD*DD];  // [n][k]: rows 0-511 = W1^T, 512-1023 = Wc1^T (tf32-RN, bias-compensated)

// ---------------- helpers ----------------
__device__ __forceinline__ uint32_t smem_u32(const void* p) {
    uint32_t a;
    asm("{ .reg .u64 t; cvta.to.shared.u64 t, %1; cvt.u32.u64 %0, t; }" : "=r"(a) : "l"(p));
    return a;
}
__device__ __forceinline__ void cp16(uint32_t dst, const void* src) {
    asm volatile("cp.async.cg.shared.global [%0], [%1], 16;" :: "r"(dst), "l"(src));
}
#define CPCOMMIT() asm volatile("cp.async.commit_group;")
#define CPWAIT1()  asm volatile("cp.async.wait_group 1;")

#define LDSM4(r, addr) \
    asm volatile("ldmatrix.sync.aligned.m8n8.x4.shared.b16 {%0,%1,%2,%3}, [%4];" \
        : "=r"((r)[0]), "=r"((r)[1]), "=r"((r)[2]), "=r"((r)[3]) : "r"(addr))

#define MMA_TF32(c, a, b0, b1) \
    asm volatile("mma.sync.aligned.m16n8k8.row.col.f32.tf32.tf32.f32 " \
        "{%0,%1,%2,%3}, {%4,%5,%6,%7}, {%8,%9}, {%0,%1,%2,%3};" \
        : "+f"((c)[0]), "+f"((c)[1]), "+f"((c)[2]), "+f"((c)[3]) \
        : "r"((a)[0]), "r"((a)[1]), "r"((a)[2]), "r"((a)[3]), "r"(b0), "r"(b1))

__device__ __forceinline__ float rna_tf32(float v) {
    uint32_t u; asm("cvt.rna.tf32.f32 %0, %1;" : "=r"(u) : "f"(v));
    return __uint_as_float(u);
}

// MUFU-free shifted softplus: max(x,0) + ln(1+e^-|x|) - ln2
__device__ __forceinline__ float sspf(float x) {
    float ax = fabsf(x);
    float u  = fmaxf(ax * -1.4426950408889634f, -30.0f);
    float fl = floorf(u);
    float z  = (u - fl) * 0.6931471805599453f;
    float p  = 1.9841270e-4f;
    p = fmaf(p, z, 1.3888889e-3f);
    p = fmaf(p, z, 8.3333333e-3f);
    p = fmaf(p, z, 4.1666667e-2f);
    p = fmaf(p, z, 1.6666667e-1f);
    p = fmaf(p, z, 0.5f);
    p = fmaf(p, z, 1.0f);
    p = fmaf(p, z, 1.0f);
    float t = __int_as_float(((int)fl + 127) << 23) * p;
    float den = 2.0f + t;
    float r = __int_as_float(0x7EF311C4u - __float_as_uint(den));
    r = r * fmaf(-den, r, 2.0f);
    r = r * fmaf(-den, r, 2.0f);
    float w  = t * r;
    float w2 = w * w;
    float q  = 0.22222222f;
    q = fmaf(q, w2, 0.28571429f);
    q = fmaf(q, w2, 0.4f);
    q = fmaf(q, w2, 0.66666667f);
    q = fmaf(q, w2, 2.0f);
    return fmaxf(x, 0.0f) + w * q - 0.6931471805599453f;
}

// ---------------- prep: weight transpose (tf32-RN + bias comp), float4 stores, + zero accumulators ----------------
__global__ void wtrans_kernel(const float* __restrict__ W1, const float* __restrict__ Wc1,
                              float* __restrict__ out) {
    __shared__ float t[32][33];
    const int tx = threadIdx.x, ty = threadIdx.y;
    const int n0 = blockIdx.x * 32, k0 = blockIdx.y * 32;
    const int n = n0 + tx;
    const float* Wsrc = (n < 512) ? (W1 + n) : (Wc1 + (n - 512));
    #pragma unroll
    for (int i = 0; i < 4; i++) {
        int k = k0 + ty * 4 + i;
        // A is fed raw f32 -> HW truncation to tf32 shrinks |a| by E[eps]~0.72*2^-11.
        // Pre-scale W to cancel the bias in expectation.
        t[ty * 4 + i][tx] = rna_tf32(Wsrc[k * 512] * 1.000352f);
    }
    __syncthreads();
    {
        float4 v = make_float4(t[ty * 4 + 0][tx], t[ty * 4 + 1][tx],
                               t[ty * 4 + 2][tx], t[ty * 4 + 3][tx]);
        *(float4*)&g_Wt[(size_t)(n0 + tx) * DD + k0 + ty * 4] = v;
    }
    int gi = (blockIdx.y * 32 + blockIdx.x) * 256 + ty * 32 + tx;
    if (gi < MMR) { g_yacc[gi] = 0.0f; g_qacc[gi] = 0.0f; }
    if (gi < BB) out[gi] = 0.0f;
}

// ---------------- tf32 mma.sync GEMM + fused ssp epilogue (R10 mainloop, frozen) ----------------
// CTA: 128x128 tile, BK=32, 8 warps (2 M x 4 N), warp tile 64x32 via m16n8k8.
// SMEM rows 128B (8 x 16B chunks), swizzle: chunk ^= (row & 7).
extern __shared__ char dynsm[];
__global__ __launch_bounds__(256, 2)
void mlp_mma(const float* __restrict__ rep,
             const float* __restrict__ b1,  const float* __restrict__ W2,
             const float* __restrict__ bc1, const float* __restrict__ Wc2)
{
    const int tid  = threadIdx.x;
    const int wid  = tid >> 5, lane = tid & 31;
    const int mw   = wid >> 2, nw = wid & 3;
    const int m0   = blockIdx.x * BM;
    const int n0   = blockIdx.y * BN;

    const uint32_t sb = smem_u32(dynsm);
    float* biasS  = (float*)(dynsm + NSTAGE * STG_BYTES);
    float* w2S    = biasS + BN;
    float* rowsum = w2S + BN;

    if (tid < BN) {
        const float* bsrc = (n0 >= 512) ? bc1 : b1;
        const float* wsrc = (n0 >= 512) ? Wc2 : W2;
        int ch = (n0 & 511) + tid;
        biasS[tid]  = bsrc[ch];
        w2S[tid]    = wsrc[ch];
        rowsum[tid] = 0.0f;
    }

    // cp.async assignments: 4 A chunks + 4 B chunks of 16B per thread
    uint32_t dstOff[4];
    const float* srcA[4];
    const float* srcB[4];
    #pragma unroll
    for (int l = 0; l < 4; l++) {
        int idx = tid + l * 256;          // 0..1023
        int row = idx >> 3, kc = idx & 7;
        dstOff[l] = row * 128 + ((kc ^ (row & 7)) << 4);
        srcA[l] = rep  + (size_t)(m0 + row) * DD + kc * 4;
        srcB[l] = g_Wt + (size_t)(n0 + row) * DD + kc * 4;
    }

    // ldmatrix per-lane base addresses (swizzled, 128B rows)
    const int g  = lane >> 3, li = lane & 7;
    const int rowA = mw * 64 + (g & 1) * 8 + li;
    const int cgA  = g >> 1;
    const uint32_t addrA0 = rowA * 128 + (((cgA ^ rowA) & 7) << 4);
    const int rowB = nw * 32 + (g >> 1) * 8 + li;
    const int cgB  = g & 1;
    const uint32_t addrB0 = rowB * 128 + (((cgB ^ rowB) & 7) << 4);

    float c[4][4][4];
    #pragma unroll
    for (int i = 0; i < 4; i++)
        #pragma unroll
        for (int j = 0; j < 4; j++)
            #pragma unroll
            for (int e = 0; e < 4; e++) c[i][j][e] = 0.0f;

    // prologue: 2 stages in flight
    #pragma unroll
    for (int s = 0; s < 2; s++) {
        uint32_t a = sb + s * STG_BYTES, b = a + 16384;
        #pragma unroll
        for (int l = 0; l < 4; l++) {
            cp16(a + dstOff[l], srcA[l] + s * BK);
            cp16(b + dstOff[l], srcB[l] + s * BK);
        }
        CPCOMMIT();
    }

    for (int it = 0; it < KITERS; it++) {
        CPWAIT1();
        __syncthreads();
        const uint32_t sA = sb + (it % 3) * STG_BYTES;
        const uint32_t sB = sA + 16384;
        const bool more = (it + 2 < KITERS);
        const uint32_t na = sb + ((it + 2) % 3) * STG_BYTES;
        const uint32_t nb = na + 16384;

        #pragma unroll
        for (int h = 0; h < 4; h++) {        // four k8 groups; ^(h*32) selects chunk pair
            const uint32_t kx = h << 5;
            uint32_t a[4][4], b[2][4];
            #pragma unroll
            for (int mt = 0; mt < 4; mt++)
                LDSM4(a[mt], sA + ((addrA0 + mt * 2048) ^ kx));
            #pragma unroll
            for (int p = 0; p < 2; p++)
                LDSM4(b[p], sB + ((addrB0 + p * 2048) ^ kx));
            #pragma unroll
            for (int mt = 0; mt < 4; mt++) {
                #pragma unroll
                for (int nt = 0; nt < 4; nt++)
                    MMA_TF32(c[mt][nt], a[mt], b[nt >> 1][(nt & 1) * 2],
                             b[nt >> 1][(nt & 1) * 2 + 1]);
            }
            // interleave next-stage loads between h-groups (off the barrier critical path)
            if (h == 0 && more) {
                #pragma unroll
                for (int l = 0; l < 4; l++) cp16(na + dstOff[l], srcA[l] + (it + 2) * BK);
            }
            if (h == 1) {
                if (more) {
                    #pragma unroll
                    for (int l = 0; l < 4; l++) cp16(nb + dstOff[l], srcB[l] + (it + 2) * BK);
                }
                CPCOMMIT();
            }
        }
    }
    __syncthreads();

    // epilogue: z+bias -> ssp -> *w2 -> per-row reduce
    float bcol[8], wcol[8];
    #pragma unroll
    for (int nt = 0; nt < 4; nt++)
        #pragma unroll
        for (int e = 0; e < 2; e++) {
            int col = nw * 32 + nt * 8 + 2 * (lane & 3) + e;
            bcol[nt * 2 + e] = biasS[col];
            wcol[nt * 2 + e] = w2S[col];
        }

    float prow[8];
    #pragma unroll
    for (int i = 0; i < 8; i++) prow[i] = 0.0f;
    #pragma unroll
    for (int mt = 0; mt < 4; mt++)
        #pragma unroll
        for (int nt = 0; nt < 4; nt++)
            #pragma unroll
            for (int e = 0; e < 4; e++) {
                float z = c[mt][nt][e] + bcol[nt * 2 + (e & 1)];
                prow[mt * 2 + (e >> 1)] += sspf(z) * wcol[nt * 2 + (e & 1)];
            }
    #pragma unroll
    for (int i = 0; i < 8; i++) {
        prow[i] += __shfl_xor_sync(0xFFFFFFFF, prow[i], 1);
        prow[i] += __shfl_xor_sync(0xFFFFFFFF, prow[i], 2);
    }
    if ((lane & 3) == 0) {
        #pragma unroll
        for (int mt = 0; mt < 4; mt++)
            #pragma unroll
            for (int hh = 0; hh < 2; hh++) {
                int rl = mw * 64 + mt * 16 + hh * 8 + (lane >> 2);
                atomicAdd(&rowsum[rl], prow[mt * 2 + hh]);
            }
    }
    __syncthreads();
    if (tid < BM) {
        float* dst = (n0 >= 512) ? g_qacc : g_yacc;
        atomicAdd(&dst[m0 + tid], rowsum[tid]);
    }
}

// ---------------- coulomb + pool: upper-triangle only (symmetric), doubled ----------------
#define CHUNK 32
__global__ __launch_bounds__(256)
void coulomb_kernel(const float* __restrict__ R, const float* __restrict__ mask,
                    const float* __restrict__ b2p, const float* __restrict__ bc2p,
                    float* __restrict__ out)
{
    const int b = blockIdx.x / (NN / CHUNK);
    const int chunk = blockIdx.x % (NN / CHUNK);
    const int tid = threadIdx.x;
    __shared__ float4 pt[NN];
    __shared__ float red[8];
    const float b2v = b2p[0], bc2v = bc2p[0];

    for (int n = tid; n < NN; n += 256) {
        float mk = mask[b * NN + n];
        float q  = (g_qacc[b * NN + n] + bc2v) * mk;
        const float* r = &R[(b * NN + n) * 3];
        pt[n] = make_float4(r[0], r[1], r[2], q);
    }
    __syncthreads();

    // pair part: j > i only (coulomb term is symmetric in i,j) -> double at the end
    float pacc = 0.0f;
    const int i0 = chunk * CHUNK;
    #pragma unroll 1
    for (int i = i0; i < i0 + CHUNK; i++) {
        const float4 pi = pt[i];
        for (int j = i + 1 + tid; j < NN; j += 256) {
            float4 pj = pt[j];
            float dx = pi.x - pj.x, dy = pi.y - pj.y, dz = pi.z - pj.z;
            float d2 = fmaf(dx, dx, fmaf(dy, dy, dz * dz));
            // hr = 1/sqrt(d2): bit-hack + 2 Newton (rel err ~3e-7)
            float hr = __int_as_float(0x5F3759DFu - (__float_as_uint(d2) >> 1));
            hr = hr * fmaf(-0.5f * d2 * hr, hr, 1.5f);
            hr = hr * fmaf(-0.5f * d2 * hr, hr, 1.5f);
            float u = 1e-5f * hr;
            // (d+eps)^-2 = hr^2 * (1 - 2u + 3u^2 + O(u^3))
            float inv2 = hr * hr * fmaf(u, fmaf(3.0f, u, -2.0f), 1.0f);
            pacc += pi.w * pj.w * inv2;
        }
    }
    // pool part (not doubled)
    float acc = pacc + pacc;
    for (int i = i0 + tid; i < i0 + CHUNK; i += 256)
        acc += (g_yacc[b * NN + i] + b2v) * mask[b * NN + i];

    #pragma unroll
    for (int off = 16; off > 0; off >>= 1) acc += __shfl_down_sync(0xFFFFFFFF, acc, off);
    if ((tid & 31) == 0) red[tid >> 5] = acc;
    __syncthreads();
    if (tid < 8) {
        float v = red[tid];
        #pragma unroll
        for (int off = 4; off > 0; off >>= 1) v += __shfl_down_sync(0xFF, v, off);
        if (tid == 0) atomicAdd(&out[b], v);
    }
}

// ---------------- host ----------------
extern "C" void kernel_launch(void* const* d_in, const int* in_sizes, int n_in,
                              void* d_out, int out_size) {
    const float* rep  = (const float*)d_in[0];
    const float* R    = (const float*)d_in[1];
    const float* mask = (const float*)d_in[2];
    const float* W1   = (const float*)d_in[3];
    const float* b1   = (const float*)d_in[4];
    const float* W2   = (const float*)d_in[5];
    const float* b2   = (const float*)d_in[6];
    const float* Wc1  = (const float*)d_in[7];
    const float* bc1  = (const float*)d_in[8];
    const float* Wc2  = (const float*)d_in[9];
    const float* bc2  = (const float*)d_in[10];
    float* out = (float*)d_out;

    const int DYN = NSTAGE * STG_BYTES + (BN * 2 + BM) * 4;   // 97.5KB
    cudaFuncSetAttribute(mlp_mma, cudaFuncAttributeMaxDynamicSharedMemorySize, DYN);

    wtrans_kernel<<<dim3(32, 32), dim3(32, 8)>>>(W1, Wc1, out);
    mlp_mma<<<dim3(MMR / BM, DD / BN), 256, DYN>>>(rep, b1, W2, bc1, Wc2);
    coulomb_kernel<<<BB * (NN / CHUNK), 256>>>(R, mask, b2, bc2, out);
}

// round 15
// speedup vs baseline: 1.4898x; 1.4620x over previous
#include <cuda_runtime.h>
#include <cuda_fp16.h>
#include <cstdint>
#include <math.h>

#define BB 32
#define NN 512
#define DD 1024
#define MMR (BB*NN)          // 16384

#define BM 128
#define BN 128
#define BK 64                // fp16: 64 k-elems = 128B rows (same swizzle as before)
#define NSTAGE 3
#define STG_BYTES 32768      // A 16KB + B 16KB per stage
#define KITERS (DD/BK)       // 16

__device__ float  g_yacc[MMR];
__device__ float  g_qacc[MMR];
__device__ __half g_Ah[MMR*DD];   // rep, fp16-RN
__device__ __half g_Wh[DD*DD];    // [n][k]: rows 0-511 = W1^T, 512-1023 = Wc1^T (fp16-RN)

// ---------------- helpers ----------------
__device__ __forceinline__ uint32_t smem_u32(const void* p) {
    uint32_t a;
    asm("{ .reg .u64 t; cvta.to.shared.u64 t, %1; cvt.u32.u64 %0, t; }" : "=r"(a) : "l"(p));
    return a;
}
__device__ __forceinline__ void cp16(uint32_t dst, const void* src) {
    asm volatile("cp.async.cg.shared.global [%0], [%1], 16;" :: "r"(dst), "l"(src));
}
#define CPCOMMIT() asm volatile("cp.async.commit_group;")
#define CPWAIT1()  asm volatile("cp.async.wait_group 1;")

#define LDSM4(r, addr) \
    asm volatile("ldmatrix.sync.aligned.m8n8.x4.shared.b16 {%0,%1,%2,%3}, [%4];" \
        : "=r"((r)[0]), "=r"((r)[1]), "=r"((r)[2]), "=r"((r)[3]) : "r"(addr))

#define MMA_F16(c, a, b0, b1) \
    asm volatile("mma.sync.aligned.m16n8k16.row.col.f32.f16.f16.f32 " \
        "{%0,%1,%2,%3}, {%4,%5,%6,%7}, {%8,%9}, {%0,%1,%2,%3};" \
        : "+f"((c)[0]), "+f"((c)[1]), "+f"((c)[2]), "+f"((c)[3]) \
        : "r"((a)[0]), "r"((a)[1]), "r"((a)[2]), "r"((a)[3]), "r"(b0), "r"(b1))

__device__ __forceinline__ uint32_t h2_bits(__half2 h) {
    return *reinterpret_cast<uint32_t*>(&h);
}

// MUFU-free shifted softplus: max(x,0) + ln(1+e^-|x|) - ln2
__device__ __forceinline__ float sspf(float x) {
    float ax = fabsf(x);
    float u  = fmaxf(ax * -1.4426950408889634f, -30.0f);
    float fl = floorf(u);
    float z  = (u - fl) * 0.6931471805599453f;
    float p  = 1.9841270e-4f;
    p = fmaf(p, z, 1.3888889e-3f);
    p = fmaf(p, z, 8.3333333e-3f);
    p = fmaf(p, z, 4.1666667e-2f);
    p = fmaf(p, z, 1.6666667e-1f);
    p = fmaf(p, z, 0.5f);
    p = fmaf(p, z, 1.0f);
    p = fmaf(p, z, 1.0f);
    float t = __int_as_float(((int)fl + 127) << 23) * p;
    float den = 2.0f + t;
    float r = __int_as_float(0x7EF311C4u - __float_as_uint(den));
    r = r * fmaf(-den, r, 2.0f);
    r = r * fmaf(-den, r, 2.0f);
    float w  = t * r;
    float w2 = w * w;
    float q  = 0.22222222f;
    q = fmaf(q, w2, 0.28571429f);
    q = fmaf(q, w2, 0.4f);
    q = fmaf(q, w2, 0.66666667f);
    q = fmaf(q, w2, 2.0f);
    return fmaxf(x, 0.0f) + w * q - 0.6931471805599453f;
}

// ---------------- prep 1: rep f32 -> fp16 RN (8 elems/thread) ----------------
__global__ void aconv_kernel(const float4* __restrict__ rep) {
    int i = blockIdx.x * 256 + threadIdx.x;      // 8 floats per thread
    float4 v0 = rep[i * 2];
    float4 v1 = rep[i * 2 + 1];
    uint4 o;
    o.x = h2_bits(__floats2half2_rn(v0.x, v0.y));
    o.y = h2_bits(__floats2half2_rn(v0.z, v0.w));
    o.z = h2_bits(__floats2half2_rn(v1.x, v1.y));
    o.w = h2_bits(__floats2half2_rn(v1.z, v1.w));
    ((uint4*)g_Ah)[i] = o;
}

// ---------------- prep 2: weight transpose -> fp16 RN + zero accumulators ----------------
__global__ void wtrans_kernel(const float* __restrict__ W1, const float* __restrict__ Wc1,
                              float* __restrict__ out) {
    __shared__ float t[32][33];
    const int tx = threadIdx.x, ty = threadIdx.y;
    const int n0 = blockIdx.x * 32, k0 = blockIdx.y * 32;
    const int n = n0 + tx;
    const float* Wsrc = (n < 512) ? (W1 + n) : (Wc1 + (n - 512));
    #pragma unroll
    for (int i = 0; i < 4; i++) {
        int k = k0 + ty * 4 + i;
        t[ty * 4 + i][tx] = Wsrc[k * 512];
    }
    __syncthreads();
    {
        uint2 o;
        o.x = h2_bits(__floats2half2_rn(t[ty * 4 + 0][tx], t[ty * 4 + 1][tx]));
        o.y = h2_bits(__floats2half2_rn(t[ty * 4 + 2][tx], t[ty * 4 + 3][tx]));
        *(uint2*)&g_Wh[(size_t)(n0 + tx) * DD + k0 + ty * 4] = o;
    }
    int gi = (blockIdx.y * 32 + blockIdx.x) * 256 + ty * 32 + tx;
    if (gi < MMR) { g_yacc[gi] = 0.0f; g_qacc[gi] = 0.0f; }
    if (gi < BB) out[gi] = 0.0f;
}

// ---------------- fp16 mma.sync GEMM + fused ssp epilogue (R10 structure, m16n8k16) ----------------
// CTA: 128x128 tile, BK=64 fp16, 8 warps (2 M x 4 N), warp tile 64x32.
// SMEM rows 128B (8 x 16B chunks), swizzle: chunk ^= (row & 7). All byte addressing identical to tf32 version.
extern __shared__ char dynsm[];
__global__ __launch_bounds__(256, 2)
void mlp_mma(const float* __restrict__ b1,  const float* __restrict__ W2,
             const float* __restrict__ bc1, const float* __restrict__ Wc2)
{
    const int tid  = threadIdx.x;
    const int wid  = tid >> 5, lane = tid & 31;
    const int mw   = wid >> 2, nw = wid & 3;
    const int m0   = blockIdx.x * BM;
    const int n0   = blockIdx.y * BN;

    const uint32_t sb = smem_u32(dynsm);
    float* biasS  = (float*)(dynsm + NSTAGE * STG_BYTES);
    float* w2S    = biasS + BN;
    float* rowsum = w2S + BN;

    if (tid < BN) {
        const float* bsrc = (n0 >= 512) ? bc1 : b1;
        const float* wsrc = (n0 >= 512) ? Wc2 : W2;
        int ch = (n0 & 511) + tid;
        biasS[tid]  = bsrc[ch];
        w2S[tid]    = wsrc[ch];
        rowsum[tid] = 0.0f;
    }

    // cp.async assignments: 4 A chunks + 4 B chunks of 16B (8 fp16) per thread
    uint32_t dstOff[4];
    const __half* srcA[4];
    const __half* srcB[4];
    #pragma unroll
    for (int l = 0; l < 4; l++) {
        int idx = tid + l * 256;          // 0..1023
        int row = idx >> 3, kc = idx & 7;
        dstOff[l] = row * 128 + ((kc ^ (row & 7)) << 4);
        srcA[l] = g_Ah + (size_t)(m0 + row) * DD + kc * 8;
        srcB[l] = g_Wh + (size_t)(n0 + row) * DD + kc * 8;
    }

    // ldmatrix per-lane base addresses (swizzled, 128B rows) — same bytes as tf32 version
    const int g  = lane >> 3, li = lane & 7;
    const int rowA = mw * 64 + (g & 1) * 8 + li;
    const int cgA  = g >> 1;
    const uint32_t addrA0 = rowA * 128 + (((cgA ^ rowA) & 7) << 4);
    const int rowB = nw * 32 + (g >> 1) * 8 + li;
    const int cgB  = g & 1;
    const uint32_t addrB0 = rowB * 128 + (((cgB ^ rowB) & 7) << 4);

    float c[4][4][4];
    #pragma unroll
    for (int i = 0; i < 4; i++)
        #pragma unroll
        for (int j = 0; j < 4; j++)
            #pragma unroll
            for (int e = 0; e < 4; e++) c[i][j][e] = 0.0f;

    // prologue: 2 stages in flight
    #pragma unroll
    for (int s = 0; s < 2; s++) {
        uint32_t a = sb + s * STG_BYTES, b = a + 16384;
        #pragma unroll
        for (int l = 0; l < 4; l++) {
            cp16(a + dstOff[l], srcA[l] + s * BK);
            cp16(b + dstOff[l], srcB[l] + s * BK);
        }
        CPCOMMIT();
    }

    for (int it = 0; it < KITERS; it++) {
        CPWAIT1();
        __syncthreads();
        const uint32_t sA = sb + (it % 3) * STG_BYTES;
        const uint32_t sB = sA + 16384;
        const bool more = (it + 2 < KITERS);
        const uint32_t na = sb + ((it + 2) % 3) * STG_BYTES;
        const uint32_t nb = na + 16384;

        #pragma unroll
        for (int h = 0; h < 4; h++) {        // four k16 groups; ^(h*32) selects 32B chunk pair
            const uint32_t kx = h << 5;
            uint32_t a[4][4], b[2][4];
            #pragma unroll
            for (int mt = 0; mt < 4; mt++)
                LDSM4(a[mt], sA + ((addrA0 + mt * 2048) ^ kx));
            #pragma unroll
            for (int p = 0; p < 2; p++)
                LDSM4(b[p], sB + ((addrB0 + p * 2048) ^ kx));
            #pragma unroll
            for (int mt = 0; mt < 4; mt++) {
                #pragma unroll
                for (int nt = 0; nt < 4; nt++)
                    MMA_F16(c[mt][nt], a[mt], b[nt >> 1][(nt & 1) * 2],
                            b[nt >> 1][(nt & 1) * 2 + 1]);
            }
            if (h == 0 && more) {
                #pragma unroll
                for (int l = 0; l < 4; l++) cp16(na + dstOff[l], srcA[l] + (it + 2) * BK);
            }
            if (h == 1) {
                if (more) {
                    #pragma unroll
                    for (int l = 0; l < 4; l++) cp16(nb + dstOff[l], srcB[l] + (it + 2) * BK);
                }
                CPCOMMIT();
            }
        }
    }
    __syncthreads();

    // epilogue: z+bias -> ssp -> *w2 -> per-row reduce
    float bcol[8], wcol[8];
    #pragma unroll
    for (int nt = 0; nt < 4; nt++)
        #pragma unroll
        for (int e = 0; e < 2; e++) {
            int col = nw * 32 + nt * 8 + 2 * (lane & 3) + e;
            bcol[nt * 2 + e] = biasS[col];
            wcol[nt * 2 + e] = w2S[col];
        }

    float prow[8];
    #pragma unroll
    for (int i = 0; i < 8; i++) prow[i] = 0.0f;
    #pragma unroll
    for (int mt = 0; mt < 4; mt++)
        #pragma unroll
        for (int nt = 0; nt < 4; nt++)
            #pragma unroll
            for (int e = 0; e < 4; e++) {
                float z = c[mt][nt][e] + bcol[nt * 2 + (e & 1)];
                prow[mt * 2 + (e >> 1)] += sspf(z) * wcol[nt * 2 + (e & 1)];
            }
    #pragma unroll
    for (int i = 0; i < 8; i++) {
        prow[i] += __shfl_xor_sync(0xFFFFFFFF, prow[i], 1);
        prow[i] += __shfl_xor_sync(0xFFFFFFFF, prow[i], 2);
    }
    if ((lane & 3) == 0) {
        #pragma unroll
        for (int mt = 0; mt < 4; mt++)
            #pragma unroll
            for (int hh = 0; hh < 2; hh++) {
                int rl = mw * 64 + mt * 16 + hh * 8 + (lane >> 2);
                atomicAdd(&rowsum[rl], prow[mt * 2 + hh]);
            }
    }
    __syncthreads();
    if (tid < BM) {
        float* dst = (n0 >= 512) ? g_qacc : g_yacc;
        atomicAdd(&dst[m0 + tid], rowsum[tid]);
    }
}

// ---------------- coulomb + pool: upper-triangle only (symmetric), doubled ----------------
#define CHUNK 32
__global__ __launch_bounds__(256)
void coulomb_kernel(const float* __restrict__ R, const float* __restrict__ mask,
                    const float* __restrict__ b2p, const float* __restrict__ bc2p,
                    float* __restrict__ out)
{
    const int b = blockIdx.x / (NN / CHUNK);
    const int chunk = blockIdx.x % (NN / CHUNK);
    const int tid = threadIdx.x;
    __shared__ float4 pt[NN];
    __shared__ float red[8];
    const float b2v = b2p[0], bc2v = bc2p[0];

    for (int n = tid; n < NN; n += 256) {
        float mk = mask[b * NN + n];
        float q  = (g_qacc[b * NN + n] + bc2v) * mk;
        const float* r = &R[(b * NN + n) * 3];
        pt[n] = make_float4(r[0], r[1], r[2], q);
    }
    __syncthreads();

    float pacc = 0.0f;
    const int i0 = chunk * CHUNK;
    #pragma unroll 1
    for (int i = i0; i < i0 + CHUNK; i++) {
        const float4 pi = pt[i];
        for (int j = i + 1 + tid; j < NN; j += 256) {
            float4 pj = pt[j];
            float dx = pi.x - pj.x, dy = pi.y - pj.y, dz = pi.z - pj.z;
            float d2 = fmaf(dx, dx, fmaf(dy, dy, dz * dz));
            float hr = __int_as_float(0x5F3759DFu - (__float_as_uint(d2) >> 1));
            hr = hr * fmaf(-0.5f * d2 * hr, hr, 1.5f);
            hr = hr * fmaf(-0.5f * d2 * hr, hr, 1.5f);
            float u = 1e-5f * hr;
            float inv2 = hr * hr * fmaf(u, fmaf(3.0f, u, -2.0f), 1.0f);
            pacc += pi.w * pj.w * inv2;
        }
    }
    float acc = pacc + pacc;
    for (int i = i0 + tid; i < i0 + CHUNK; i += 256)
        acc += (g_yacc[b * NN + i] + b2v) * mask[b * NN + i];

    #pragma unroll
    for (int off = 16; off > 0; off >>= 1) acc += __shfl_down_sync(0xFFFFFFFF, acc, off);
    if ((tid & 31) == 0) red[tid >> 5] = acc;
    __syncthreads();
    if (tid < 8) {
        float v = red[tid];
        #pragma unroll
        for (int off = 4; off > 0; off >>= 1) v += __shfl_down_sync(0xFF, v, off);
        if (tid == 0) atomicAdd(&out[b], v);
    }
}

// ---------------- host ----------------
extern "C" void kernel_launch(void* const* d_in, const int* in_sizes, int n_in,
                              void* d_out, int out_size) {
    const float* rep  = (const float*)d_in[0];
    const float* R    = (const float*)d_in[1];
    const float* mask = (const float*)d_in[2];
    const float* W1   = (const float*)d_in[3];
    const float* b1   = (const float*)d_in[4];
    const float* W2   = (const float*)d_in[5];
    const float* b2   = (const float*)d_in[6];
    const float* Wc1  = (const float*)d_in[7];
    const float* bc1  = (const float*)d_in[8];
    const float* Wc2  = (const float*)d_in[9];
    const float* bc2  = (const float*)d_in[10];
    float* out = (float*)d_out;

    const int DYN = NSTAGE * STG_BYTES + (BN * 2 + BM) * 4;   // 97.5KB
    cudaFuncSetAttribute(mlp_mma, cudaFuncAttributeMaxDynamicSharedMemorySize, DYN);

    aconv_kernel<<<(MMR * DD / 8) / 256, 256>>>((const float4*)rep);
    wtrans_kernel<<<dim3(32, 32), dim3(32, 8)>>>(W1, Wc1, out);
    mlp_mma<<<dim3(MMR / BM, DD / BN), 256, DYN>>>(b1, W2, bc1, Wc2);
    coulomb_kernel<<<BB * (NN / CHUNK), 256>>>(R, mask, b2, bc2, out);
}

// round 16
// speedup vs baseline: 1.5111x; 1.0143x over previous
#include <cuda_runtime.h>
#include <cuda_fp16.h>
#include <cstdint>
#include <math.h>

#define BB 32
#define NN 512
#define DD 1024
#define MMR (BB*NN)          // 16384

#define BM 128
#define BN 128
#define BK 64                // fp16: 64 k-elems = 128B rows
#define NSTAGE 3
#define STG_BYTES 32768      // A 16KB + B 16KB per stage
#define KITERS (DD/BK)       // 16

__device__ float  g_yacc[MMR];
__device__ float  g_qacc[MMR];
__device__ __half g_Ah[MMR*DD];   // rep, fp16-RN
__device__ __half g_Wh[DD*DD];    // [n][k]: rows 0-511 = W1^T, 512-1023 = Wc1^T (fp16-RN)

// ---------------- helpers ----------------
__device__ __forceinline__ uint32_t smem_u32(const void* p) {
    uint32_t a;
    asm("{ .reg .u64 t; cvta.to.shared.u64 t, %1; cvt.u32.u64 %0, t; }" : "=r"(a) : "l"(p));
    return a;
}
__device__ __forceinline__ void cp16(uint32_t dst, const void* src) {
    asm volatile("cp.async.cg.shared.global [%0], [%1], 16;" :: "r"(dst), "l"(src));
}
#define CPCOMMIT() asm volatile("cp.async.commit_group;")
#define CPWAIT1()  asm volatile("cp.async.wait_group 1;")

#define LDSM4(r, addr) \
    asm volatile("ldmatrix.sync.aligned.m8n8.x4.shared.b16 {%0,%1,%2,%3}, [%4];" \
        : "=r"((r)[0]), "=r"((r)[1]), "=r"((r)[2]), "=r"((r)[3]) : "r"(addr))

#define MMA_F16(c, a, b0, b1) \
    asm volatile("mma.sync.aligned.m16n8k16.row.col.f32.f16.f16.f32 " \
        "{%0,%1,%2,%3}, {%4,%5,%6,%7}, {%8,%9}, {%0,%1,%2,%3};" \
        : "+f"((c)[0]), "+f"((c)[1]), "+f"((c)[2]), "+f"((c)[3]) \
        : "r"((a)[0]), "r"((a)[1]), "r"((a)[2]), "r"((a)[3]), "r"(b0), "r"(b1))

__device__ __forceinline__ uint32_t h2_bits(__half2 h) {
    return *reinterpret_cast<uint32_t*>(&h);
}

// MUFU-free shifted softplus: max(x,0) + ln(1+e^-|x|) - ln2
__device__ __forceinline__ float sspf(float x) {
    float ax = fabsf(x);
    float u  = fmaxf(ax * -1.4426950408889634f, -30.0f);
    float fl = floorf(u);
    float z  = (u - fl) * 0.6931471805599453f;
    float p  = 1.9841270e-4f;
    p = fmaf(p, z, 1.3888889e-3f);
    p = fmaf(p, z, 8.3333333e-3f);
    p = fmaf(p, z, 4.1666667e-2f);
    p = fmaf(p, z, 1.6666667e-1f);
    p = fmaf(p, z, 0.5f);
    p = fmaf(p, z, 1.0f);
    p = fmaf(p, z, 1.0f);
    float t = __int_as_float(((int)fl + 127) << 23) * p;
    float den = 2.0f + t;
    float r = __int_as_float(0x7EF311C4u - __float_as_uint(den));
    r = r * fmaf(-den, r, 2.0f);
    r = r * fmaf(-den, r, 2.0f);
    float w  = t * r;
    float w2 = w * w;
    float q  = 0.22222222f;
    q = fmaf(q, w2, 0.28571429f);
    q = fmaf(q, w2, 0.4f);
    q = fmaf(q, w2, 0.66666667f);
    q = fmaf(q, w2, 2.0f);
    return fmaxf(x, 0.0f) + w * q - 0.6931471805599453f;
}

// ---------------- prep 1: rep f32 -> fp16 RN (8 elems/thread) ----------------
__global__ void aconv_kernel(const float4* __restrict__ rep) {
    int i = blockIdx.x * 256 + threadIdx.x;      // 8 floats per thread
    float4 v0 = rep[i * 2];
    float4 v1 = rep[i * 2 + 1];
    uint4 o;
    o.x = h2_bits(__floats2half2_rn(v0.x, v0.y));
    o.y = h2_bits(__floats2half2_rn(v0.z, v0.w));
    o.z = h2_bits(__floats2half2_rn(v1.x, v1.y));
    o.w = h2_bits(__floats2half2_rn(v1.z, v1.w));
    ((uint4*)g_Ah)[i] = o;
}

// ---------------- prep 2: weight transpose -> fp16 RN + zero accumulators ----------------
__global__ void wtrans_kernel(const float* __restrict__ W1, const float* __restrict__ Wc1,
                              float* __restrict__ out) {
    __shared__ float t[32][33];
    const int tx = threadIdx.x, ty = threadIdx.y;
    const int n0 = blockIdx.x * 32, k0 = blockIdx.y * 32;
    const int n = n0 + tx;
    const float* Wsrc = (n < 512) ? (W1 + n) : (Wc1 + (n - 512));
    #pragma unroll
    for (int i = 0; i < 4; i++) {
        int k = k0 + ty * 4 + i;
        t[ty * 4 + i][tx] = Wsrc[k * 512];
    }
    __syncthreads();
    {
        uint2 o;
        o.x = h2_bits(__floats2half2_rn(t[ty * 4 + 0][tx], t[ty * 4 + 1][tx]));
        o.y = h2_bits(__floats2half2_rn(t[ty * 4 + 2][tx], t[ty * 4 + 3][tx]));
        *(uint2*)&g_Wh[(size_t)(n0 + tx) * DD + k0 + ty * 4] = o;
    }
    int gi = (blockIdx.y * 32 + blockIdx.x) * 256 + ty * 32 + tx;
    if (gi < MMR) { g_yacc[gi] = 0.0f; g_qacc[gi] = 0.0f; }
    if (gi < BB) out[gi] = 0.0f;
}

// ---------------- fp16 mma.sync GEMM + fused ssp epilogue (frozen R15 mainloop) ----------------
// CTA: 128x128 tile, BK=64 fp16, 8 warps (2 M x 4 N), warp tile 64x32.
// SMEM rows 128B (8 x 16B chunks), swizzle: chunk ^= (row & 7).
extern __shared__ char dynsm[];
__global__ __launch_bounds__(256, 2)
void mlp_mma(const float* __restrict__ b1,  const float* __restrict__ W2,
             const float* __restrict__ bc1, const float* __restrict__ Wc2)
{
    const int tid  = threadIdx.x;
    const int wid  = tid >> 5, lane = tid & 31;
    const int mw   = wid >> 2, nw = wid & 3;
    const int m0   = blockIdx.x * BM;
    const int n0   = blockIdx.y * BN;

    const uint32_t sb = smem_u32(dynsm);
    float* biasS  = (float*)(dynsm + NSTAGE * STG_BYTES);
    float* w2S    = biasS + BN;
    float* rowsum = w2S + BN;

    if (tid < BN) {
        const float* bsrc = (n0 >= 512) ? bc1 : b1;
        const float* wsrc = (n0 >= 512) ? Wc2 : W2;
        int ch = (n0 & 511) + tid;
        biasS[tid]  = bsrc[ch];
        w2S[tid]    = wsrc[ch];
        rowsum[tid] = 0.0f;
    }

    // cp.async assignments: 4 A chunks + 4 B chunks of 16B (8 fp16) per thread
    uint32_t dstOff[4];
    const __half* srcA[4];
    const __half* srcB[4];
    #pragma unroll
    for (int l = 0; l < 4; l++) {
        int idx = tid + l * 256;          // 0..1023
        int row = idx >> 3, kc = idx & 7;
        dstOff[l] = row * 128 + ((kc ^ (row & 7)) << 4);
        srcA[l] = g_Ah + (size_t)(m0 + row) * DD + kc * 8;
        srcB[l] = g_Wh + (size_t)(n0 + row) * DD + kc * 8;
    }

    // ldmatrix per-lane base addresses (swizzled, 128B rows)
    const int g  = lane >> 3, li = lane & 7;
    const int rowA = mw * 64 + (g & 1) * 8 + li;
    const int cgA  = g >> 1;
    const uint32_t addrA0 = rowA * 128 + (((cgA ^ rowA) & 7) << 4);
    const int rowB = nw * 32 + (g >> 1) * 8 + li;
    const int cgB  = g & 1;
    const uint32_t addrB0 = rowB * 128 + (((cgB ^ rowB) & 7) << 4);

    float c[4][4][4];
    #pragma unroll
    for (int i = 0; i < 4; i++)
        #pragma unroll
        for (int j = 0; j < 4; j++)
            #pragma unroll
            for (int e = 0; e < 4; e++) c[i][j][e] = 0.0f;

    // prologue: 2 stages in flight
    #pragma unroll
    for (int s = 0; s < 2; s++) {
        uint32_t a = sb + s * STG_BYTES, b = a + 16384;
        #pragma unroll
        for (int l = 0; l < 4; l++) {
            cp16(a + dstOff[l], srcA[l] + s * BK);
            cp16(b + dstOff[l], srcB[l] + s * BK);
        }
        CPCOMMIT();
    }

    for (int it = 0; it < KITERS; it++) {
        CPWAIT1();
        __syncthreads();
        const uint32_t sA = sb + (it % 3) * STG_BYTES;
        const uint32_t sB = sA + 16384;
        const bool more = (it + 2 < KITERS);
        const uint32_t na = sb + ((it + 2) % 3) * STG_BYTES;
        const uint32_t nb = na + 16384;

        #pragma unroll
        for (int h = 0; h < 4; h++) {        // four k16 groups; ^(h*32) selects 32B chunk pair
            const uint32_t kx = h << 5;
            uint32_t a[4][4], b[2][4];
            #pragma unroll
            for (int mt = 0; mt < 4; mt++)
                LDSM4(a[mt], sA + ((addrA0 + mt * 2048) ^ kx));
            #pragma unroll
            for (int p = 0; p < 2; p++)
                LDSM4(b[p], sB + ((addrB0 + p * 2048) ^ kx));
            #pragma unroll
            for (int mt = 0; mt < 4; mt++) {
                #pragma unroll
                for (int nt = 0; nt < 4; nt++)
                    MMA_F16(c[mt][nt], a[mt], b[nt >> 1][(nt & 1) * 2],
                            b[nt >> 1][(nt & 1) * 2 + 1]);
            }
            if (h == 0 && more) {
                #pragma unroll
                for (int l = 0; l < 4; l++) cp16(na + dstOff[l], srcA[l] + (it + 2) * BK);
            }
            if (h == 1) {
                if (more) {
                    #pragma unroll
                    for (int l = 0; l < 4; l++) cp16(nb + dstOff[l], srcB[l] + (it + 2) * BK);
                }
                CPCOMMIT();
            }
        }
    }
    __syncthreads();

    // epilogue: z+bias -> ssp -> *w2 -> per-row reduce
    float bcol[8], wcol[8];
    #pragma unroll
    for (int nt = 0; nt < 4; nt++)
        #pragma unroll
        for (int e = 0; e < 2; e++) {
            int col = nw * 32 + nt * 8 + 2 * (lane & 3) + e;
            bcol[nt * 2 + e] = biasS[col];
            wcol[nt * 2 + e] = w2S[col];
        }

    float prow[8];
    #pragma unroll
    for (int i = 0; i < 8; i++) prow[i] = 0.0f;
    #pragma unroll
    for (int mt = 0; mt < 4; mt++)
        #pragma unroll
        for (int nt = 0; nt < 4; nt++)
            #pragma unroll
            for (int e = 0; e < 4; e++) {
                float z = c[mt][nt][e] + bcol[nt * 2 + (e & 1)];
                prow[mt * 2 + (e >> 1)] += sspf(z) * wcol[nt * 2 + (e & 1)];
            }
    #pragma unroll
    for (int i = 0; i < 8; i++) {
        prow[i] += __shfl_xor_sync(0xFFFFFFFF, prow[i], 1);
        prow[i] += __shfl_xor_sync(0xFFFFFFFF, prow[i], 2);
    }
    if ((lane & 3) == 0) {
        #pragma unroll
        for (int mt = 0; mt < 4; mt++)
            #pragma unroll
            for (int hh = 0; hh < 2; hh++) {
                int rl = mw * 64 + mt * 16 + hh * 8 + (lane >> 2);
                atomicAdd(&rowsum[rl], prow[mt * 2 + hh]);
            }
    }
    __syncthreads();
    if (tid < BM) {
        float* dst = (n0 >= 512) ? g_qacc : g_yacc;
        atomicAdd(&dst[m0 + tid], rowsum[tid]);
    }
}

// ---------------- coulomb + pool: upper triangle, mirrored-chunk pairing for balance ----------------
// Block handles chunks c and NCH-1-c: total pair work per block is uniform across c.
#define CHUNK 32
#define NCH (NN / CHUNK)        // 16
__global__ __launch_bounds__(256)
void coulomb_kernel(const float* __restrict__ R, const float* __restrict__ mask,
                    const float* __restrict__ b2p, const float* __restrict__ bc2p,
                    float* __restrict__ out)
{
    const int b  = blockIdx.x / (NCH / 2);
    const int cc = blockIdx.x % (NCH / 2);       // 0..7
    const int tid = threadIdx.x;
    __shared__ float4 pt[NN];
    __shared__ float red[8];
    const float b2v = b2p[0], bc2v = bc2p[0];

    for (int n = tid; n < NN; n += 256) {
        float mk = mask[b * NN + n];
        float q  = (g_qacc[b * NN + n] + bc2v) * mk;
        const float* r = &R[(b * NN + n) * 3];
        pt[n] = make_float4(r[0], r[1], r[2], q);
    }
    __syncthreads();

    float pacc = 0.0f;
    float pool = 0.0f;
    #pragma unroll
    for (int half = 0; half < 2; half++) {
        const int chunk = half ? (NCH - 1 - cc) : cc;
        const int i0 = chunk * CHUNK;
        #pragma unroll 1
        for (int i = i0; i < i0 + CHUNK; i++) {
            const float4 pi = pt[i];
            for (int j = i + 1 + tid; j < NN; j += 256) {
                float4 pj = pt[j];
                float dx = pi.x - pj.x, dy = pi.y - pj.y, dz = pi.z - pj.z;
                float d2 = fmaf(dx, dx, fmaf(dy, dy, dz * dz));
                float hr = __int_as_float(0x5F3759DFu - (__float_as_uint(d2) >> 1));
                hr = hr * fmaf(-0.5f * d2 * hr, hr, 1.5f);
                hr = hr * fmaf(-0.5f * d2 * hr, hr, 1.5f);
                float u = 1e-5f * hr;
                float inv2 = hr * hr * fmaf(u, fmaf(3.0f, u, -2.0f), 1.0f);
                pacc += pi.w * pj.w * inv2;
            }
        }
        for (int i = i0 + tid; i < i0 + CHUNK; i += 256)
            pool += (g_yacc[b * NN + i] + b2v) * mask[b * NN + i];
    }
    float acc = pacc + pacc + pool;

    #pragma unroll
    for (int off = 16; off > 0; off >>= 1) acc += __shfl_down_sync(0xFFFFFFFF, acc, off);
    if ((tid & 31) == 0) red[tid >> 5] = acc;
    __syncthreads();
    if (tid < 8) {
        float v = red[tid];
        #pragma unroll
        for (int off = 4; off > 0; off >>= 1) v += __shfl_down_sync(0xFF, v, off);
        if (tid == 0) atomicAdd(&out[b], v);
    }
}

// ---------------- host ----------------
extern "C" void kernel_launch(void* const* d_in, const int* in_sizes, int n_in,
                              void* d_out, int out_size) {
    const float* rep  = (const float*)d_in[0];
    const float* R    = (const float*)d_in[1];
    const float* mask = (const float*)d_in[2];
    const float* W1   = (const float*)d_in[3];
    const float* b1   = (const float*)d_in[4];
    const float* W2   = (const float*)d_in[5];
    const float* b2   = (const float*)d_in[6];
    const float* Wc1  = (const float*)d_in[7];
    const float* bc1  = (const float*)d_in[8];
    const float* Wc2  = (const float*)d_in[9];
    const float* bc2  = (const float*)d_in[10];
    float* out = (float*)d_out;

    const int DYN = NSTAGE * STG_BYTES + (BN * 2 + BM) * 4;   // 97.5KB
    cudaFuncSetAttribute(mlp_mma, cudaFuncAttributeMaxDynamicSharedMemorySize, DYN);

    aconv_kernel<<<(MMR * DD / 8) / 256, 256>>>((const float4*)rep);
    wtrans_kernel<<<dim3(32, 32), dim3(32, 8)>>>(W1, Wc1, out);
    mlp_mma<<<dim3(MMR / BM, DD / BN), 256, DYN>>>(b1, W2, bc1, Wc2);
    coulomb_kernel<<<BB * (NCH / 2), 256>>>(R, mask, b2, bc2, out);
}

// round 17
// speedup vs baseline: 1.5361x; 1.0166x over previous
#include <cuda_runtime.h>
#include <cuda_fp16.h>
#include <cstdint>
#include <math.h>

#define BB 32
#define NN 512
#define DD 1024
#define MMR (BB*NN)          // 16384

#define BM 128
#define BN 128
#define BK 64                // fp16: 64 k-elems = 128B rows
#define NSTAGE 3
#define STG_BYTES 32768      // A 16KB + B 16KB per stage
#define KITERS (DD/BK)       // 16

__device__ float  g_yacc[MMR];
__device__ float  g_qacc[MMR];
__device__ __half g_Ah[MMR*DD];   // rep, fp16-RN
__device__ __half g_Wh[DD*DD];    // [n][k]: rows 0-511 = W1^T, 512-1023 = Wc1^T (fp16-RN)

// ---------------- helpers ----------------
__device__ __forceinline__ uint32_t smem_u32(const void* p) {
    uint32_t a;
    asm("{ .reg .u64 t; cvta.to.shared.u64 t, %1; cvt.u32.u64 %0, t; }" : "=r"(a) : "l"(p));
    return a;
}
__device__ __forceinline__ void cp16(uint32_t dst, const void* src) {
    asm volatile("cp.async.cg.shared.global [%0], [%1], 16;" :: "r"(dst), "l"(src));
}
#define CPCOMMIT() asm volatile("cp.async.commit_group;")
#define CPWAIT1()  asm volatile("cp.async.wait_group 1;")

#define LDSM4(r, addr) \
    asm volatile("ldmatrix.sync.aligned.m8n8.x4.shared.b16 {%0,%1,%2,%3}, [%4];" \
        : "=r"((r)[0]), "=r"((r)[1]), "=r"((r)[2]), "=r"((r)[3]) : "r"(addr))

#define MMA_F16(c, a, b0, b1) \
    asm volatile("mma.sync.aligned.m16n8k16.row.col.f32.f16.f16.f32 " \
        "{%0,%1,%2,%3}, {%4,%5,%6,%7}, {%8,%9}, {%0,%1,%2,%3};" \
        : "+f"((c)[0]), "+f"((c)[1]), "+f"((c)[2]), "+f"((c)[3]) \
        : "r"((a)[0]), "r"((a)[1]), "r"((a)[2]), "r"((a)[3]), "r"(b0), "r"(b1))

__device__ __forceinline__ uint32_t h2_bits(__half2 h) {
    return *reinterpret_cast<uint32_t*>(&h);
}

// MUFU-free shifted softplus: max(x,0) + ln(1+e^-|x|) - ln2
__device__ __forceinline__ float sspf(float x) {
    float ax = fabsf(x);
    float u  = fmaxf(ax * -1.4426950408889634f, -30.0f);
    float fl = floorf(u);
    float z  = (u - fl) * 0.6931471805599453f;
    float p  = 1.9841270e-4f;
    p = fmaf(p, z, 1.3888889e-3f);
    p = fmaf(p, z, 8.3333333e-3f);
    p = fmaf(p, z, 4.1666667e-2f);
    p = fmaf(p, z, 1.6666667e-1f);
    p = fmaf(p, z, 0.5f);
    p = fmaf(p, z, 1.0f);
    p = fmaf(p, z, 1.0f);
    float t = __int_as_float(((int)fl + 127) << 23) * p;
    float den = 2.0f + t;
    float r = __int_as_float(0x7EF311C4u - __float_as_uint(den));
    r = r * fmaf(-den, r, 2.0f);
    r = r * fmaf(-den, r, 2.0f);
    float w  = t * r;
    float w2 = w * w;
    float q  = 0.22222222f;
    q = fmaf(q, w2, 0.28571429f);
    q = fmaf(q, w2, 0.4f);
    q = fmaf(q, w2, 0.66666667f);
    q = fmaf(q, w2, 2.0f);
    return fmaxf(x, 0.0f) + w * q - 0.6931471805599453f;
}

// ---------------- prep 1: rep f32 -> fp16 RN (8 elems/thread) ----------------
__global__ void aconv_kernel(const float4* __restrict__ rep) {
    int i = blockIdx.x * 256 + threadIdx.x;      // 8 floats per thread
    float4 v0 = rep[i * 2];
    float4 v1 = rep[i * 2 + 1];
    uint4 o;
    o.x = h2_bits(__floats2half2_rn(v0.x, v0.y));
    o.y = h2_bits(__floats2half2_rn(v0.z, v0.w));
    o.z = h2_bits(__floats2half2_rn(v1.x, v1.y));
    o.w = h2_bits(__floats2half2_rn(v1.z, v1.w));
    ((uint4*)g_Ah)[i] = o;
}

// ---------------- prep 2: weight transpose -> fp16 RN + zero accumulators ----------------
__global__ void wtrans_kernel(const float* __restrict__ W1, const float* __restrict__ Wc1,
                              float* __restrict__ out) {
    __shared__ float t[32][33];
    const int tx = threadIdx.x, ty = threadIdx.y;
    const int n0 = blockIdx.x * 32, k0 = blockIdx.y * 32;
    const int n = n0 + tx;
    const float* Wsrc = (n < 512) ? (W1 + n) : (Wc1 + (n - 512));
    #pragma unroll
    for (int i = 0; i < 4; i++) {
        int k = k0 + ty * 4 + i;
        t[ty * 4 + i][tx] = Wsrc[k * 512];
    }
    __syncthreads();
    {
        uint2 o;
        o.x = h2_bits(__floats2half2_rn(t[ty * 4 + 0][tx], t[ty * 4 + 1][tx]));
        o.y = h2_bits(__floats2half2_rn(t[ty * 4 + 2][tx], t[ty * 4 + 3][tx]));
        *(uint2*)&g_Wh[(size_t)(n0 + tx) * DD + k0 + ty * 4] = o;
    }
    int gi = (blockIdx.y * 32 + blockIdx.x) * 256 + ty * 32 + tx;
    if (gi < MMR) { g_yacc[gi] = 0.0f; g_qacc[gi] = 0.0f; }
    if (gi < BB) out[gi] = 0.0f;
}

// ---------------- fp16 mma.sync GEMM + fused ssp epilogue (frozen R15 mainloop) ----------------
// CTA: 128x128 tile, BK=64 fp16, 8 warps (2 M x 4 N), warp tile 64x32.
// SMEM rows 128B (8 x 16B chunks), swizzle: chunk ^= (row & 7).
extern __shared__ char dynsm[];
__global__ __launch_bounds__(256, 2)
void mlp_mma(const float* __restrict__ b1,  const float* __restrict__ W2,
             const float* __restrict__ bc1, const float* __restrict__ Wc2)
{
    const int tid  = threadIdx.x;
    const int wid  = tid >> 5, lane = tid & 31;
    const int mw   = wid >> 2, nw = wid & 3;
    const int m0   = blockIdx.x * BM;
    const int n0   = blockIdx.y * BN;

    const uint32_t sb = smem_u32(dynsm);
    float* biasS  = (float*)(dynsm + NSTAGE * STG_BYTES);
    float* w2S    = biasS + BN;
    float* rowsum = w2S + BN;

    if (tid < BN) {
        const float* bsrc = (n0 >= 512) ? bc1 : b1;
        const float* wsrc = (n0 >= 512) ? Wc2 : W2;
        int ch = (n0 & 511) + tid;
        biasS[tid]  = bsrc[ch];
        w2S[tid]    = wsrc[ch];
        rowsum[tid] = 0.0f;
    }

    // cp.async assignments: 4 A chunks + 4 B chunks of 16B (8 fp16) per thread
    uint32_t dstOff[4];
    const __half* srcA[4];
    const __half* srcB[4];
    #pragma unroll
    for (int l = 0; l < 4; l++) {
        int idx = tid + l * 256;          // 0..1023
        int row = idx >> 3, kc = idx & 7;
        dstOff[l] = row * 128 + ((kc ^ (row & 7)) << 4);
        srcA[l] = g_Ah + (size_t)(m0 + row) * DD + kc * 8;
        srcB[l] = g_Wh + (size_t)(n0 + row) * DD + kc * 8;
    }

    // ldmatrix per-lane base addresses (swizzled, 128B rows)
    const int g  = lane >> 3, li = lane & 7;
    const int rowA = mw * 64 + (g & 1) * 8 + li;
    const int cgA  = g >> 1;
    const uint32_t addrA0 = rowA * 128 + (((cgA ^ rowA) & 7) << 4);
    const int rowB = nw * 32 + (g >> 1) * 8 + li;
    const int cgB  = g & 1;
    const uint32_t addrB0 = rowB * 128 + (((cgB ^ rowB) & 7) << 4);

    float c[4][4][4];
    #pragma unroll
    for (int i = 0; i < 4; i++)
        #pragma unroll
        for (int j = 0; j < 4; j++)
            #pragma unroll
            for (int e = 0; e < 4; e++) c[i][j][e] = 0.0f;

    // prologue: 2 stages in flight
    #pragma unroll
    for (int s = 0; s < 2; s++) {
        uint32_t a = sb + s * STG_BYTES, b = a + 16384;
        #pragma unroll
        for (int l = 0; l < 4; l++) {
            cp16(a + dstOff[l], srcA[l] + s * BK);
            cp16(b + dstOff[l], srcB[l] + s * BK);
        }
        CPCOMMIT();
    }

    for (int it = 0; it < KITERS; it++) {
        CPWAIT1();
        __syncthreads();
        const uint32_t sA = sb + (it % 3) * STG_BYTES;
        const uint32_t sB = sA + 16384;
        const bool more = (it + 2 < KITERS);
        const uint32_t na = sb + ((it + 2) % 3) * STG_BYTES;
        const uint32_t nb = na + 16384;

        #pragma unroll
        for (int h = 0; h < 4; h++) {        // four k16 groups; ^(h*32) selects 32B chunk pair
            const uint32_t kx = h << 5;
            uint32_t a[4][4], b[2][4];
            #pragma unroll
            for (int mt = 0; mt < 4; mt++)
                LDSM4(a[mt], sA + ((addrA0 + mt * 2048) ^ kx));
            #pragma unroll
            for (int p = 0; p < 2; p++)
                LDSM4(b[p], sB + ((addrB0 + p * 2048) ^ kx));
            #pragma unroll
            for (int mt = 0; mt < 4; mt++) {
                #pragma unroll
                for (int nt = 0; nt < 4; nt++)
                    MMA_F16(c[mt][nt], a[mt], b[nt >> 1][(nt & 1) * 2],
                            b[nt >> 1][(nt & 1) * 2 + 1]);
            }
            if (h == 0 && more) {
                #pragma unroll
                for (int l = 0; l < 4; l++) cp16(na + dstOff[l], srcA[l] + (it + 2) * BK);
            }
            if (h == 1) {
                if (more) {
                    #pragma unroll
                    for (int l = 0; l < 4; l++) cp16(nb + dstOff[l], srcB[l] + (it + 2) * BK);
                }
                CPCOMMIT();
            }
        }
    }
    __syncthreads();

    // epilogue: z+bias -> ssp -> *w2 -> per-row reduce
    float bcol[8], wcol[8];
    #pragma unroll
    for (int nt = 0; nt < 4; nt++)
        #pragma unroll
        for (int e = 0; e < 2; e++) {
            int col = nw * 32 + nt * 8 + 2 * (lane & 3) + e;
            bcol[nt * 2 + e] = biasS[col];
            wcol[nt * 2 + e] = w2S[col];
        }

    float prow[8];
    #pragma unroll
    for (int i = 0; i < 8; i++) prow[i] = 0.0f;
    #pragma unroll
    for (int mt = 0; mt < 4; mt++)
        #pragma unroll
        for (int nt = 0; nt < 4; nt++)
            #pragma unroll
            for (int e = 0; e < 4; e++) {
                float z = c[mt][nt][e] + bcol[nt * 2 + (e & 1)];
                prow[mt * 2 + (e >> 1)] += sspf(z) * wcol[nt * 2 + (e & 1)];
            }
    #pragma unroll
    for (int i = 0; i < 8; i++) {
        prow[i] += __shfl_xor_sync(0xFFFFFFFF, prow[i], 1);
        prow[i] += __shfl_xor_sync(0xFFFFFFFF, prow[i], 2);
    }
    if ((lane & 3) == 0) {
        #pragma unroll
        for (int mt = 0; mt < 4; mt++)
            #pragma unroll
            for (int hh = 0; hh < 2; hh++) {
                int rl = mw * 64 + mt * 16 + hh * 8 + (lane >> 2);
                atomicAdd(&rowsum[rl], prow[mt * 2 + hh]);
            }
    }
    __syncthreads();
    if (tid < BM) {
        float* dst = (n0 >= 512) ? g_qacc : g_yacc;
        atomicAdd(&dst[m0 + tid], rowsum[tid]);
    }
}

// ---------------- coulomb + pool: full pairs, uniform per-thread work (measured-fast form) ----------------
#define CHUNK 32
__global__ __launch_bounds__(256)
void coulomb_kernel(const float* __restrict__ R, const float* __restrict__ mask,
                    const float* __restrict__ b2p, const float* __restrict__ bc2p,
                    float* __restrict__ out)
{
    const int b = blockIdx.x / (NN / CHUNK);
    const int chunk = blockIdx.x % (NN / CHUNK);
    const int tid = threadIdx.x;
    __shared__ float4 pt[NN];
    __shared__ float red[8];
    const float b2v = b2p[0], bc2v = bc2p[0];

    for (int n = tid; n < NN; n += 256) {
        float mk = mask[b * NN + n];
        float q  = (g_qacc[b * NN + n] + bc2v) * mk;
        const float* r = &R[(b * NN + n) * 3];
        pt[n] = make_float4(r[0], r[1], r[2], q);
    }
    __syncthreads();

    float acc = 0.0f;
    const int i0 = chunk * CHUNK;
    #pragma unroll 1
    for (int i = i0; i < i0 + CHUNK; i += 2) {
        const float4 p0 = pt[i];
        const float4 p1 = pt[i + 1];
        #pragma unroll 2
        for (int j = tid; j < NN; j += 256) {
            float4 pj = pt[j];
            {
                float dx = p0.x - pj.x, dy = p0.y - pj.y, dz = p0.z - pj.z;
                float d2 = fmaf(dx, dx, fmaf(dy, dy, dz * dz));
                float hr = __int_as_float(0x5F3759DFu - (__float_as_uint(d2) >> 1));
                hr = hr * fmaf(-0.5f * d2 * hr, hr, 1.5f);
                hr = hr * fmaf(-0.5f * d2 * hr, hr, 1.5f);
                float u = 1e-5f * hr;
                float inv2 = hr * hr * fmaf(u, fmaf(3.0f, u, -2.0f), 1.0f);
                float tt = p0.w * pj.w * inv2;
                acc += (j == i) ? 0.0f : tt;
            }
            {
                float dx = p1.x - pj.x, dy = p1.y - pj.y, dz = p1.z - pj.z;
                float d2 = fmaf(dx, dx, fmaf(dy, dy, dz * dz));
                float hr = __int_as_float(0x5F3759DFu - (__float_as_uint(d2) >> 1));
                hr = hr * fmaf(-0.5f * d2 * hr, hr, 1.5f);
                hr = hr * fmaf(-0.5f * d2 * hr, hr, 1.5f);
                float u = 1e-5f * hr;
                float inv2 = hr * hr * fmaf(u, fmaf(3.0f, u, -2.0f), 1.0f);
                float tt = p1.w * pj.w * inv2;
                acc += (j == i + 1) ? 0.0f : tt;
            }
        }
    }
    for (int i = i0 + tid; i < i0 + CHUNK; i += 256)
        acc += (g_yacc[b * NN + i] + b2v) * mask[b * NN + i];

    #pragma unroll
    for (int off = 16; off > 0; off >>= 1) acc += __shfl_down_sync(0xFFFFFFFF, acc, off);
    if ((tid & 31) == 0) red[tid >> 5] = acc;
    __syncthreads();
    if (tid < 8) {
        float v = red[tid];
        #pragma unroll
        for (int off = 4; off > 0; off >>= 1) v += __shfl_down_sync(0xFF, v, off);
        if (tid == 0) atomicAdd(&out[b], v);
    }
}

// ---------------- host ----------------
extern "C" void kernel_launch(void* const* d_in, const int* in_sizes, int n_in,
                              void* d_out, int out_size) {
    const float* rep  = (const float*)d_in[0];
    const float* R    = (const float*)d_in[1];
    const float* mask = (const float*)d_in[2];
    const float* W1   = (const float*)d_in[3];
    const float* b1   = (const float*)d_in[4];
    const float* W2   = (const float*)d_in[5];
    const float* b2   = (const float*)d_in[6];
    const float* Wc1  = (const float*)d_in[7];
    const float* bc1  = (const float*)d_in[8];
    const float* Wc2  = (const float*)d_in[9];
    const float* bc2  = (const float*)d_in[10];
    float* out = (float*)d_out;

    const int DYN = NSTAGE * STG_BYTES + (BN * 2 + BM) * 4;   // 97.5KB
    cudaFuncSetAttribute(mlp_mma, cudaFuncAttributeMaxDynamicSharedMemorySize, DYN);

    aconv_kernel<<<(MMR * DD / 8) / 256, 256>>>((const float4*)rep);
    wtrans_kernel<<<dim3(32, 32), dim3(32, 8)>>>(W1, Wc1, out);
    mlp_mma<<<dim3(MMR / BM, DD / BN), 256, DYN>>>(b1, W2, bc1, Wc2);
    coulomb_kernel<<<BB * (NN / CHUNK), 256>>>(R, mask, b2, bc2, out);
}